// round 5
// baseline (speedup 1.0000x reference)
#include <cuda_runtime.h>
#include <cstdint>

#define NB    64
#define TE    200
#define ENCD  256
#define DECD  1024
#define HATT  128
#define NCONV 32
#define KCONV 31
#define PADC  15
#define PRE   256
#define NC    80
#define TFEAT 1000
#define SSTEPS 500
#define HSZ   (NB*DECD)

#define LOGIT_OFF 5120000
#define ATTW_OFF  5184000

#define GRID  128
#define THR   256

// total dynamic smem: As 4*2*16*68 = 8704 floats, Ws 4*2*16*36 = 4608 floats
#define SMEM_FLOATS 13312
#define WS_OFF      8704

// ---------------- scratch ----------------
__device__ float g_pm[NB*TE*HATT];
__device__ float g_Wck[HATT*32];
__device__ float g_preH[SSTEPS*NB*PRE];
__device__ float g_P[SSTEPS*NB*PRE];
__device__ float g_ac4[4*NB*ENCD];           // 4-slot rotating attention context
__device__ float g_h0[2*HSZ], g_c0[HSZ];
__device__ float g_h1[2*HSZ], g_c1[HSZ];
__device__ float g_acc[NB*TE];
__device__ float g_b40[4096], g_b41[4096];   // combined biases bih+bhh
__device__ unsigned g_bar;

// ---------------- f32x2 helpers (PTX-only dual-FMA pipe) ----------------
__device__ __forceinline__ void fma2(unsigned long long& d, unsigned long long a, unsigned long long b) {
    asm("fma.rn.f32x2 %0, %1, %2, %0;" : "+l"(d) : "l"(a), "l"(b));
}
__device__ __forceinline__ void add2(unsigned long long& d, unsigned long long a) {
    asm("add.rn.f32x2 %0, %0, %1;" : "+l"(d) : "l"(a));
}
__device__ __forceinline__ unsigned long long dupf(float x) {
    unsigned long long r; asm("mov.b64 %0, {%1, %1};" : "=l"(r) : "f"(x)); return r;
}
__device__ __forceinline__ float2 unp(unsigned long long v) {
    float2 r; asm("mov.b64 {%0, %1}, %2;" : "=f"(r.x), "=f"(r.y) : "l"(v)); return r;
}
union F4U { float4 f; unsigned long long u[2]; };

// ---------------- grid barrier (monotonic counter) ----------------
__device__ __forceinline__ void gbar(unsigned target) {
    __syncthreads();
    if (threadIdx.x == 0) {
        __threadfence();
        atomicAdd(&g_bar, 1u);
        while (*(volatile unsigned*)&g_bar < target) { }
        __threadfence();
    }
    __syncthreads();
}

// ---------------- setup kernels ----------------
__global__ void k_wck(const float* __restrict__ watt, const float* __restrict__ cw) {
    int idx = blockIdx.x * blockDim.x + threadIdx.x;
    if (idx >= HATT * 32) return;
    int h = idx >> 5, k = idx & 31;
    float s = 0.f;
    if (k < KCONV) {
        #pragma unroll
        for (int c = 0; c < NCONV; c++) s += watt[h * NCONV + c] * cw[c * KCONV + k];
    }
    g_Wck[idx] = s;
}

__global__ void k_init(const float* __restrict__ b0a, const float* __restrict__ b0b,
                       const float* __restrict__ b1a, const float* __restrict__ b1b) {
    int i = blockIdx.x * blockDim.x + threadIdx.x;
    if (i == 0) g_bar = 0u;
    if (i < 2 * HSZ) { g_h0[i] = 0.f; g_h1[i] = 0.f; }
    if (i < HSZ)     { g_c0[i] = 0.f; g_c1[i] = 0.f; }
    if (i < 4096)    { g_b40[i] = b0a[i] + b0b[i]; g_b41[i] = b1a[i] + b1b[i]; }
}

// ---------------- setup GEMM (validated in R3):  C = A*W^T (+bias, relu) -------
template<int LOADER>
__global__ __launch_bounds__(256) void k_gemm(
    const float* __restrict__ A, const float* __restrict__ W,
    const float* __restrict__ bias, float* __restrict__ Cout,
    int N, int K, int lda, const float* __restrict__ ft, int relu)
{
    __shared__ float As[16][68];
    __shared__ float Ws[16][68];
    int tid  = threadIdx.x;
    int mb = blockIdx.x * 64, nb = blockIdx.y * 64;
    int la_m = tid >> 2, la_k = (tid & 3) << 2;
    int tx = tid & 15, ty = tid >> 4;
    float acc[4][4] = {};

    for (int k0 = 0; k0 < K; k0 += 16) {
        float4 av;
        if (LOADER == 0) {
            av = *reinterpret_cast<const float4*>(A + (size_t)(mb + la_m) * lda + k0 + la_k);
        } else {
            int row = mb + la_m;
            int s = row >> 6, bb = row & 63;
            float t0 = 0.f, t1 = 0.f, t2 = 0.f, t3 = 0.f;
            if (s > 0) {
                int base = (s - 1) * 2;
                int k = k0 + la_k;
                const float* fb = ft + (size_t)bb * NC * TFEAT;
                t0 = fb[(k % NC) * TFEAT + base + k / NC]; k++;
                t1 = fb[(k % NC) * TFEAT + base + k / NC]; k++;
                t2 = fb[(k % NC) * TFEAT + base + k / NC]; k++;
                t3 = fb[(k % NC) * TFEAT + base + k / NC];
            }
            av = make_float4(t0, t1, t2, t3);
        }
        As[la_k][la_m] = av.x; As[la_k+1][la_m] = av.y;
        As[la_k+2][la_m] = av.z; As[la_k+3][la_m] = av.w;
        float4 wv = *reinterpret_cast<const float4*>(W + (size_t)(nb + la_m) * K + k0 + la_k);
        Ws[la_k][la_m] = wv.x; Ws[la_k+1][la_m] = wv.y;
        Ws[la_k+2][la_m] = wv.z; Ws[la_k+3][la_m] = wv.w;
        __syncthreads();
        #pragma unroll
        for (int k = 0; k < 16; k++) {
            float4 a = *reinterpret_cast<const float4*>(&As[k][ty << 2]);
            float4 b = *reinterpret_cast<const float4*>(&Ws[k][tx << 2]);
            acc[0][0] += a.x*b.x; acc[0][1] += a.x*b.y; acc[0][2] += a.x*b.z; acc[0][3] += a.x*b.w;
            acc[1][0] += a.y*b.x; acc[1][1] += a.y*b.y; acc[1][2] += a.y*b.z; acc[1][3] += a.y*b.w;
            acc[2][0] += a.z*b.x; acc[2][1] += a.z*b.y; acc[2][2] += a.z*b.z; acc[2][3] += a.z*b.w;
            acc[3][0] += a.w*b.x; acc[3][1] += a.w*b.y; acc[3][2] += a.w*b.z; acc[3][3] += a.w*b.w;
        }
        __syncthreads();
    }
    #pragma unroll
    for (int i = 0; i < 4; i++) {
        int m = mb + (ty << 2) + i;
        #pragma unroll
        for (int j = 0; j < 4; j++) {
            int n = nb + (tx << 2) + j;
            float v = acc[i][j] + bias[n];
            if (relu) v = fmaxf(v, 0.f);
            Cout[(size_t)m * N + n] = v;
        }
    }
}

// ---------------- fused LSTM tile: GEMM (f32x2, 4-way K-split) + pointwise -------
#define ASR(g,b,k,m) smem_f[ ((((g)*2+(b))*16 + (k))*68) + (m) ]
#define WSR(g,b,k,n) smem_f[ WS_OFF + ((((g)*2+(b))*16 + (k))*36) + (n) ]

template<int L>
__device__ void lstm_tile(float* __restrict__ smem_f, int u0,
    const float* __restrict__ ac, const float* __restrict__ Ps,
    const float* __restrict__ h0r, const float* __restrict__ h1r,
    const float* __restrict__ wih, const float* __restrict__ whh,
    const float* __restrict__ b4,
    const float* __restrict__ hprev, float* __restrict__ hout, float* __restrict__ cio)
{
    constexpr int K   = L ? 2048 : 1536;
    constexpr int Kq  = K / 4;
    constexpr int KIH = L ? 1024 : 512;
    constexpr int NT  = Kq / 16;

    const int t = threadIdx.x;
    const int la_m = t >> 2, la_k = (t & 3) << 2;
    const int wg = t >> 6, t6 = t & 63;
    const int lw_n = t6 >> 1, lw_k = (t6 & 1) << 3;
    const int grow = (lw_n & 3) * 1024 + u0 + (lw_n >> 2);
    const float* wih_row = wih + (size_t)grow * KIH;
    const float* whh_row = whh + (size_t)grow * 1024;
    const int ty = t6 >> 2, tx = t6 & 3;

    auto ldA = [&](int kabs) -> float4 {
        if (L == 0) {
            if (kabs < 256)  return *reinterpret_cast<const float4*>(ac  + la_m * 256 + kabs);
            if (kabs < 512)  return *reinterpret_cast<const float4*>(Ps  + la_m * 256 + (kabs - 256));
            return *reinterpret_cast<const float4*>(h0r + la_m * 1024 + (kabs - 512));
        } else {
            if (kabs < 1024) return *reinterpret_cast<const float4*>(h0r + la_m * 1024 + kabs);
            return *reinterpret_cast<const float4*>(h1r + la_m * 1024 + (kabs - 1024));
        }
    };
    auto ldW = [&](int kabs) -> float4 {
        return (kabs < KIH) ? *reinterpret_cast<const float4*>(wih_row + kabs)
                            : *reinterpret_cast<const float4*>(whh_row + (kabs - KIH));
    };

    float4 aR[4], wR0, wR1;
    #pragma unroll
    for (int j = 0; j < 4; j++) aR[j] = ldA(j * Kq + la_k);
    wR0 = ldW(wg * Kq + lw_k);
    wR1 = ldW(wg * Kq + lw_k + 4);
    #pragma unroll
    for (int j = 0; j < 4; j++) {
        ASR(j,0,la_k+0,la_m) = aR[j].x; ASR(j,0,la_k+1,la_m) = aR[j].y;
        ASR(j,0,la_k+2,la_m) = aR[j].z; ASR(j,0,la_k+3,la_m) = aR[j].w;
    }
    WSR(wg,0,lw_k+0,lw_n)=wR0.x; WSR(wg,0,lw_k+1,lw_n)=wR0.y;
    WSR(wg,0,lw_k+2,lw_n)=wR0.z; WSR(wg,0,lw_k+3,lw_n)=wR0.w;
    WSR(wg,0,lw_k+4,lw_n)=wR1.x; WSR(wg,0,lw_k+5,lw_n)=wR1.y;
    WSR(wg,0,lw_k+6,lw_n)=wR1.z; WSR(wg,0,lw_k+7,lw_n)=wR1.w;
    __syncthreads();

    unsigned long long acc[4][4];
    #pragma unroll
    for (int m = 0; m < 4; m++)
        #pragma unroll
        for (int p = 0; p < 4; p++) acc[m][p] = 0ull;

    for (int i = 0; i < NT; i++) {
        int buf = i & 1;
        bool more = (i + 1 < NT);
        if (more) {
            int kb = (i + 1) * 16;
            #pragma unroll
            for (int j = 0; j < 4; j++) aR[j] = ldA(j * Kq + kb + la_k);
            wR0 = ldW(wg * Kq + kb + lw_k);
            wR1 = ldW(wg * Kq + kb + lw_k + 4);
        }
        #pragma unroll
        for (int k = 0; k < 16; k++) {
            float4 a = *reinterpret_cast<const float4*>(&ASR(wg, buf, k, ty << 2));
            F4U b0, b1;
            b0.f = *reinterpret_cast<const float4*>(&WSR(wg, buf, k, tx << 3));
            b1.f = *reinterpret_cast<const float4*>(&WSR(wg, buf, k, (tx << 3) + 4));
            unsigned long long d;
            d = dupf(a.x);
            fma2(acc[0][0], d, b0.u[0]); fma2(acc[0][1], d, b0.u[1]);
            fma2(acc[0][2], d, b1.u[0]); fma2(acc[0][3], d, b1.u[1]);
            d = dupf(a.y);
            fma2(acc[1][0], d, b0.u[0]); fma2(acc[1][1], d, b0.u[1]);
            fma2(acc[1][2], d, b1.u[0]); fma2(acc[1][3], d, b1.u[1]);
            d = dupf(a.z);
            fma2(acc[2][0], d, b0.u[0]); fma2(acc[2][1], d, b0.u[1]);
            fma2(acc[2][2], d, b1.u[0]); fma2(acc[2][3], d, b1.u[1]);
            d = dupf(a.w);
            fma2(acc[3][0], d, b0.u[0]); fma2(acc[3][1], d, b0.u[1]);
            fma2(acc[3][2], d, b1.u[0]); fma2(acc[3][3], d, b1.u[1]);
        }
        if (more) {
            int nb = buf ^ 1;
            #pragma unroll
            for (int j = 0; j < 4; j++) {
                ASR(j,nb,la_k+0,la_m) = aR[j].x; ASR(j,nb,la_k+1,la_m) = aR[j].y;
                ASR(j,nb,la_k+2,la_m) = aR[j].z; ASR(j,nb,la_k+3,la_m) = aR[j].w;
            }
            WSR(wg,nb,lw_k+0,lw_n)=wR0.x; WSR(wg,nb,lw_k+1,lw_n)=wR0.y;
            WSR(wg,nb,lw_k+2,lw_n)=wR0.z; WSR(wg,nb,lw_k+3,lw_n)=wR0.w;
            WSR(wg,nb,lw_k+4,lw_n)=wR1.x; WSR(wg,nb,lw_k+5,lw_n)=wR1.y;
            WSR(wg,nb,lw_k+6,lw_n)=wR1.z; WSR(wg,nb,lw_k+7,lw_n)=wR1.w;
        }
        __syncthreads();
    }

    // cross-group reduction into group 0
    unsigned long long* red = reinterpret_cast<unsigned long long*>(smem_f);
    if (wg > 0) {
        unsigned long long* dst = red + ((size_t)((wg - 1) * 64 + t6)) * 16;
        #pragma unroll
        for (int q = 0; q < 16; q++) dst[q] = acc[q >> 2][q & 3];
    }
    __syncthreads();
    if (wg == 0) {
        #pragma unroll
        for (int r = 0; r < 3; r++) {
            unsigned long long* src = red + ((size_t)(r * 64 + t6)) * 16;
            #pragma unroll
            for (int q = 0; q < 16; q++) add2(acc[q >> 2][q & 3], src[q]);
        }
        // inline pointwise + zoneout: thread owns 4 batches x 2 hidden units
        #pragma unroll
        for (int m = 0; m < 4; m++) {
            int b = (ty << 2) + m;
            #pragma unroll
            for (int hh = 0; hh < 2; hh++) {
                int u = u0 + (tx << 1) + hh;
                float2 p01 = unp(acc[m][2 * hh]);
                float2 p23 = unp(acc[m][2 * hh + 1]);
                float gi = p01.x + b4[u];
                float gf = p01.y + b4[1024 + u];
                float gg = p23.x + b4[2048 + u];
                float go = p23.y + b4[3072 + u];
                int idx = b * 1024 + u;
                float cold = cio[idx], hold = hprev[idx];
                float si = 1.f / (1.f + __expf(-gi));
                float sf = 1.f / (1.f + __expf(-gf));
                float so = 1.f / (1.f + __expf(-go));
                float c2 = sf * cold + si * tanhf(gg);
                float h2 = so * tanhf(c2);
                hout[idx] = 0.1f * hold + 0.9f * h2;
                cio[idx]  = 0.1f * cold + 0.9f * c2;
            }
        }
    }
    __syncthreads();
}

// ---------------- attention (validated math, device-fn form) ----------------
__device__ void att_step(float* __restrict__ smem_f, int s, int b,
    const float* __restrict__ enc, const int* __restrict__ text_len,
    const float* __restrict__ wdec, const float* __restrict__ watt,
    const float* __restrict__ watt_b,
    const float* __restrict__ h0cur, float* __restrict__ ac_out,
    float* __restrict__ attw_out)
{
    float* sWck = smem_f;               // 4224
    float* apad = smem_f + 4224;        // 232
    float* dp   = smem_f + 4456;        // 128
    float* w_s  = smem_f + 4584;        // 128
    float* sE   = smem_f + 4712;        // 200
    float* red  = smem_f + 4912;        // 16
    int tid = threadIdx.x, lane = tid & 31, wid = tid >> 5;
    int len = text_len[b];

    for (int i = tid; i < HATT * 33; i += THR) {
        int h = i / 33, k = i - h * 33;
        sWck[i] = (k < 31) ? g_Wck[h * 32 + k] : 0.f;
    }
    if (tid < 16)  apad[tid] = 0.f;
    if (tid < 17)  apad[215 + tid] = 0.f;
    if (tid < 200) {
        float v = (s == 0) ? ((tid < len) ? 1.f / (float)len : 0.f) : g_acc[b * TE + tid];
        apad[PADC + tid] = v;
    }
    if (tid < HATT) w_s[tid] = watt[tid];

    {
        const float* hr = h0cur + b * DECD;
        for (int h = wid; h < HATT; h += 8) {
            const float* wr = wdec + (size_t)h * DECD;
            float p = 0.f;
            #pragma unroll 8
            for (int j = lane; j < DECD; j += 32) p += wr[j] * hr[j];
            #pragma unroll
            for (int o = 16; o; o >>= 1) p += __shfl_xor_sync(0xffffffffu, p, o);
            if (lane == 0) dp[h] = p;
        }
    }
    __syncthreads();

    const float wb0 = watt_b[0];
    for (int it = 0; it < 25; it++) {
        int t = it * 8 + wid;
        const float* pmrow = g_pm + ((size_t)(b * TE + t)) * HATT;
        float esum = 0.f;
        #pragma unroll
        for (int hh = 0; hh < 4; hh++) {
            int h = lane + (hh << 5);
            const float* wc = sWck + h * 33;
            float conv = 0.f;
            #pragma unroll
            for (int k = 0; k < 31; k++) conv += wc[k] * apad[t + k];
            float x = conv + dp[h] + pmrow[h];
            float ez = __expf(2.f * x);
            float th = 1.f - __fdividef(2.f, ez + 1.f);
            esum += w_s[h] * th;
        }
        #pragma unroll
        for (int o = 16; o; o >>= 1) esum += __shfl_xor_sync(0xffffffffu, esum, o);
        if (lane == 0) sE[t] = esum + wb0;
    }
    __syncthreads();

    float e = (tid < len) ? sE[tid] : -1e30f;
    float mx = e;
    #pragma unroll
    for (int o = 16; o; o >>= 1) mx = fmaxf(mx, __shfl_xor_sync(0xffffffffu, mx, o));
    if (lane == 0) red[wid] = mx;
    __syncthreads();
    if (tid == 0) {
        float mm = red[0];
        for (int i = 1; i < 8; i++) mm = fmaxf(mm, red[i]);
        red[8] = mm;
    }
    __syncthreads();
    mx = red[8];
    float ex = __expf(e - mx);
    float sm = ex;
    #pragma unroll
    for (int o = 16; o; o >>= 1) sm += __shfl_xor_sync(0xffffffffu, sm, o);
    if (lane == 0) red[wid] = sm;
    __syncthreads();
    if (tid == 0) {
        float ss = 0.f;
        for (int i = 0; i < 8; i++) ss += red[i];
        red[9] = ss;
    }
    __syncthreads();
    float inv = 1.f / red[9];
    __syncthreads();
    if (tid < 200) {
        float aw = ex * inv;
        sE[tid] = aw;
        attw_out[((size_t)b * SSTEPS + s) * TE + tid] = aw;
        float an = (s == 0) ? aw : g_acc[b * TE + tid] + aw;
        g_acc[b * TE + tid] = an;
    }
    __syncthreads();

    {
        int c = tid;
        const float* er = enc + ((size_t)b * TE) * ENCD + c;
        float a0 = 0.f, a1 = 0.f, a2 = 0.f, a3 = 0.f;
        #pragma unroll 4
        for (int t = 0; t < TE; t += 4) {
            a0 += sE[t]     * er[(size_t)t * ENCD];
            a1 += sE[t + 1] * er[(size_t)(t + 1) * ENCD];
            a2 += sE[t + 2] * er[(size_t)(t + 2) * ENCD];
            a3 += sE[t + 3] * er[(size_t)(t + 3) * ENCD];
        }
        ac_out[b * ENCD + c] = (a0 + a1) + (a2 + a3);
    }
    __syncthreads();
}

// ---------------- output projection ----------------
__device__ void outproj(float* __restrict__ smem_f, int s, int b,
    const float* __restrict__ h1cur, const float* __restrict__ acbuf,
    const float* __restrict__ fw, const float* __restrict__ pwm,
    const float* __restrict__ pb, float* __restrict__ out)
{
    float* hcs = smem_f;
    int tid = threadIdx.x, lane = tid & 31, wid = tid >> 5;
    for (int i = tid; i < 1280; i += THR)
        hcs[i] = (i < 1024) ? h1cur[b * DECD + i] : acbuf[b * ENCD + (i - 1024)];
    __syncthreads();
    for (int o = wid; o < 162; o += 8) {
        const float* row = (o < 160) ? (fw + (size_t)o * 1280) : (pwm + (size_t)(o - 160) * 1280);
        float sum = 0.f;
        #pragma unroll 4
        for (int i = lane; i < 1280; i += 32) sum += hcs[i] * row[i];
        #pragma unroll
        for (int of = 16; of; of >>= 1) sum += __shfl_xor_sync(0xffffffffu, sum, of);
        if (lane == 0) {
            if (o < 160) {
                int r = o / NC, ch = o % NC;
                out[(size_t)b * NC * TFEAT + (size_t)ch * TFEAT + s * 2 + r] = sum;
            } else {
                out[LOGIT_OFF + (size_t)b * TFEAT + s * 2 + (o - 160)] = sum + pb[o - 160];
            }
        }
    }
    __syncthreads();
}

// ---------------- persistent decoder ----------------
__global__ void __launch_bounds__(THR, 1) k_decoder(
    const float* __restrict__ enc, const int* __restrict__ tlen,
    const float* __restrict__ wdec, const float* __restrict__ watt,
    const float* __restrict__ wattb,
    const float* __restrict__ l0wih, const float* __restrict__ l0whh,
    const float* __restrict__ l1wih, const float* __restrict__ l1whh,
    const float* __restrict__ fow, const float* __restrict__ pow_,
    const float* __restrict__ pob, float* __restrict__ out)
{
    extern __shared__ float smem_f[];
    int blk = blockIdx.x;
    unsigned gen = 0;
    float* attw = out + ATTW_OFF;

    // P0: attention for step 0 (h0 = 0, uniform prior)
    if (blk < 64)
        att_step(smem_f, 0, blk, enc, tlen, wdec, watt, wattb, g_h0, g_ac4, attw);
    gen++; gbar(gen * GRID);

    for (int s = 0; s < SSTEPS; s++) {
        int p = s & 1;
        const float* Ps = g_P + (size_t)s * NB * PRE;
        // P2: lstm0 (all 128 blocks)
        lstm_tile<0>(smem_f, blk * 8,
                     g_ac4 + (size_t)(s & 3) * NB * ENCD, Ps,
                     g_h0 + (size_t)p * HSZ, nullptr,
                     l0wih, l0whh, g_b40,
                     g_h0 + (size_t)p * HSZ, g_h0 + (size_t)(p ^ 1) * HSZ, g_c0);
        gen++; gbar(gen * GRID);
        // P3: lstm1 (all) || att(s+1) on blocks 0-63 || outproj(s-1) on blocks 64-127
        lstm_tile<1>(smem_f, blk * 8,
                     nullptr, nullptr,
                     g_h0 + (size_t)(p ^ 1) * HSZ, g_h1 + (size_t)p * HSZ,
                     l1wih, l1whh, g_b41,
                     g_h1 + (size_t)p * HSZ, g_h1 + (size_t)(p ^ 1) * HSZ, g_c1);
        if (blk < 64) {
            if (s + 1 < SSTEPS)
                att_step(smem_f, s + 1, blk, enc, tlen, wdec, watt, wattb,
                         g_h0 + (size_t)(p ^ 1) * HSZ,
                         g_ac4 + (size_t)((s + 1) & 3) * NB * ENCD, attw);
        } else {
            if (s >= 1)
                outproj(smem_f, s - 1, blk - 64,
                        g_h1 + (size_t)(s & 1) * HSZ,
                        g_ac4 + (size_t)((s - 1) & 3) * NB * ENCD,
                        fow, pow_, pob, out);
        }
        gen++; gbar(gen * GRID);
    }
    // tail: outproj for the last step
    if (blk < 64)
        outproj(smem_f, SSTEPS - 1, blk,
                g_h1 + (size_t)(SSTEPS & 1) * HSZ,
                g_ac4 + (size_t)((SSTEPS - 1) & 3) * NB * ENCD,
                fow, pow_, pob, out);
}

// ---------------- host ----------------
static float* symaddr(const void* sym) {
    void* p = nullptr;
    cudaGetSymbolAddress(&p, sym);
    return (float*)p;
}

extern "C" void kernel_launch(void* const* d_in, const int* in_sizes, int n_in,
                              void* d_out, int out_size)
{
    const float* enc    = (const float*)d_in[0];
    const int*   tlen   = (const int*)  d_in[1];
    const float* ft     = (const float*)d_in[2];
    const float* enc_w  = (const float*)d_in[3];
    const float* enc_b  = (const float*)d_in[4];
    const float* dec_w  = (const float*)d_in[5];
    const float* att_w  = (const float*)d_in[6];
    const float* conv_w = (const float*)d_in[7];
    const float* ww     = (const float*)d_in[8];
    const float* wbb    = (const float*)d_in[9];
    const float* pw0    = (const float*)d_in[10];
    const float* pb0    = (const float*)d_in[11];
    const float* pw1    = (const float*)d_in[12];
    const float* pb1    = (const float*)d_in[13];
    const float* l0wih  = (const float*)d_in[14];
    const float* l0whh  = (const float*)d_in[15];
    const float* l0bih  = (const float*)d_in[16];
    const float* l0bhh  = (const float*)d_in[17];
    const float* l1wih  = (const float*)d_in[18];
    const float* l1whh  = (const float*)d_in[19];
    const float* l1bih  = (const float*)d_in[20];
    const float* l1bhh  = (const float*)d_in[21];
    const float* fow    = (const float*)d_in[22];
    const float* pow_   = (const float*)d_in[23];
    const float* pob    = (const float*)d_in[24];
    float* out = (float*)d_out;

    float* pm_p = symaddr(g_pm);
    float* preH = symaddr(g_preH);
    float* Pp   = symaddr(g_P);

    static int smem_set = 0;
    if (!smem_set) {
        cudaFuncSetAttribute(k_decoder, cudaFuncAttributeMaxDynamicSharedMemorySize,
                             SMEM_FLOATS * 4);
        smem_set = 1;
    }

    // setup (6 graph nodes total)
    k_wck<<<16, 256>>>(att_w, conv_w);
    k_init<<<(2 * HSZ + 255) / 256, 256>>>(l0bih, l0bhh, l1bih, l1bhh);
    k_gemm<0><<<dim3(200, 2), 256>>>(enc, enc_w, enc_b, pm_p, 128, 256, 256, nullptr, 0);
    k_gemm<1><<<dim3(500, 4), 256>>>(nullptr, pw0, pb0, preH, 256, 160, 0, ft, 1);
    k_gemm<0><<<dim3(500, 4), 256>>>(preH, pw1, pb1, Pp, 256, 256, 256, nullptr, 1);

    k_decoder<<<GRID, THR, SMEM_FLOATS * 4>>>(
        enc, tlen, dec_w, ww, wbb,
        l0wih, l0whh, l1wih, l1whh,
        fow, pow_, pob, out);
}

// round 6
// speedup vs baseline: 1.0366x; 1.0366x over previous
#include <cuda_runtime.h>
#include <cstdint>

#define NB    64
#define TE    200
#define ENCD  256
#define DECD  1024
#define HATT  128
#define NCONV 32
#define KCONV 31
#define PADC  15
#define PRE   256
#define NC    80
#define TFEAT 1000
#define SSTEPS 500
#define HSZ   (NB*DECD)

#define LOGIT_OFF 5120000
#define ATTW_OFF  5184000

#define GRID  128
#define THR   256

// total dynamic smem: As 4*2*16*68 = 8704 floats, Ws 4*2*16*36 = 4608 floats
#define SMEM_FLOATS 13312
#define WS_OFF      8704

// ---------------- scratch ----------------
__device__ float g_pm[NB*TE*HATT];
__device__ float g_Wck[HATT*32];
__device__ float g_preH[SSTEPS*NB*PRE];
__device__ float g_P[SSTEPS*NB*PRE];
__device__ float g_ac4[4*NB*ENCD];           // 4-slot rotating attention context
__device__ float g_h0[2*HSZ], g_c0[HSZ];
__device__ float g_h1[2*HSZ], g_c1[HSZ];
__device__ float g_acc[NB*TE];
__device__ float g_b40[4096], g_b41[4096];   // combined biases bih+bhh
__device__ unsigned g_bar;

// ---------------- f32x2 helpers (PTX-only dual-FMA pipe) ----------------
__device__ __forceinline__ void fma2(unsigned long long& d, unsigned long long a, unsigned long long b) {
    asm("fma.rn.f32x2 %0, %1, %2, %0;" : "+l"(d) : "l"(a), "l"(b));
}
__device__ __forceinline__ void add2(unsigned long long& d, unsigned long long a) {
    asm("add.rn.f32x2 %0, %0, %1;" : "+l"(d) : "l"(a));
}
__device__ __forceinline__ unsigned long long dupf(float x) {
    unsigned long long r; asm("mov.b64 %0, {%1, %1};" : "=l"(r) : "f"(x)); return r;
}
__device__ __forceinline__ float2 unp(unsigned long long v) {
    float2 r; asm("mov.b64 {%0, %1}, %2;" : "=f"(r.x), "=f"(r.y) : "l"(v)); return r;
}
union F4U { float4 f; unsigned long long u[2]; };

// ---------------- grid barrier (monotonic counter) ----------------
__device__ __forceinline__ void gbar(unsigned target) {
    __syncthreads();
    if (threadIdx.x == 0) {
        __threadfence();
        atomicAdd(&g_bar, 1u);
        while (*(volatile unsigned*)&g_bar < target) { }
        __threadfence();
    }
    __syncthreads();
}

// ---------------- setup kernels ----------------
__global__ void k_wck(const float* __restrict__ watt, const float* __restrict__ cw) {
    int idx = blockIdx.x * blockDim.x + threadIdx.x;
    if (idx >= HATT * 32) return;
    int h = idx >> 5, k = idx & 31;
    float s = 0.f;
    if (k < KCONV) {
        #pragma unroll
        for (int c = 0; c < NCONV; c++) s += watt[h * NCONV + c] * cw[c * KCONV + k];
    }
    g_Wck[idx] = s;
}

__global__ void k_init(const float* __restrict__ b0a, const float* __restrict__ b0b,
                       const float* __restrict__ b1a, const float* __restrict__ b1b) {
    int i = blockIdx.x * blockDim.x + threadIdx.x;
    if (i == 0) g_bar = 0u;
    if (i < 2 * HSZ) { g_h0[i] = 0.f; g_h1[i] = 0.f; }
    if (i < HSZ)     { g_c0[i] = 0.f; g_c1[i] = 0.f; }
    if (i < 4096)    { g_b40[i] = b0a[i] + b0b[i]; g_b41[i] = b1a[i] + b1b[i]; }
}

// ---------------- setup GEMM (validated in R3):  C = A*W^T (+bias, relu) -------
template<int LOADER>
__global__ __launch_bounds__(256) void k_gemm(
    const float* __restrict__ A, const float* __restrict__ W,
    const float* __restrict__ bias, float* __restrict__ Cout,
    int N, int K, int lda, const float* __restrict__ ft, int relu)
{
    __shared__ float As[16][68];
    __shared__ float Ws[16][68];
    int tid  = threadIdx.x;
    int mb = blockIdx.x * 64, nb = blockIdx.y * 64;
    int la_m = tid >> 2, la_k = (tid & 3) << 2;
    int tx = tid & 15, ty = tid >> 4;
    float acc[4][4] = {};

    for (int k0 = 0; k0 < K; k0 += 16) {
        float4 av;
        if (LOADER == 0) {
            av = *reinterpret_cast<const float4*>(A + (size_t)(mb + la_m) * lda + k0 + la_k);
        } else {
            int row = mb + la_m;
            int s = row >> 6, bb = row & 63;
            float t0 = 0.f, t1 = 0.f, t2 = 0.f, t3 = 0.f;
            if (s > 0) {
                int base = (s - 1) * 2;
                int k = k0 + la_k;
                const float* fb = ft + (size_t)bb * NC * TFEAT;
                t0 = fb[(k % NC) * TFEAT + base + k / NC]; k++;
                t1 = fb[(k % NC) * TFEAT + base + k / NC]; k++;
                t2 = fb[(k % NC) * TFEAT + base + k / NC]; k++;
                t3 = fb[(k % NC) * TFEAT + base + k / NC];
            }
            av = make_float4(t0, t1, t2, t3);
        }
        As[la_k][la_m] = av.x; As[la_k+1][la_m] = av.y;
        As[la_k+2][la_m] = av.z; As[la_k+3][la_m] = av.w;
        float4 wv = *reinterpret_cast<const float4*>(W + (size_t)(nb + la_m) * K + k0 + la_k);
        Ws[la_k][la_m] = wv.x; Ws[la_k+1][la_m] = wv.y;
        Ws[la_k+2][la_m] = wv.z; Ws[la_k+3][la_m] = wv.w;
        __syncthreads();
        #pragma unroll
        for (int k = 0; k < 16; k++) {
            float4 a = *reinterpret_cast<const float4*>(&As[k][ty << 2]);
            float4 b = *reinterpret_cast<const float4*>(&Ws[k][tx << 2]);
            acc[0][0] += a.x*b.x; acc[0][1] += a.x*b.y; acc[0][2] += a.x*b.z; acc[0][3] += a.x*b.w;
            acc[1][0] += a.y*b.x; acc[1][1] += a.y*b.y; acc[1][2] += a.y*b.z; acc[1][3] += a.y*b.w;
            acc[2][0] += a.z*b.x; acc[2][1] += a.z*b.y; acc[2][2] += a.z*b.z; acc[2][3] += a.z*b.w;
            acc[3][0] += a.w*b.x; acc[3][1] += a.w*b.y; acc[3][2] += a.w*b.z; acc[3][3] += a.w*b.w;
        }
        __syncthreads();
    }
    #pragma unroll
    for (int i = 0; i < 4; i++) {
        int m = mb + (ty << 2) + i;
        #pragma unroll
        for (int j = 0; j < 4; j++) {
            int n = nb + (tx << 2) + j;
            float v = acc[i][j] + bias[n];
            if (relu) v = fmaxf(v, 0.f);
            Cout[(size_t)m * N + n] = v;
        }
    }
}

// ---------------- fused LSTM tile: GEMM (f32x2, 4-way K-split) + pointwise -------
#define ASR(g,b,k,m) smem_f[ ((((g)*2+(b))*16 + (k))*68) + (m) ]
#define WSR(g,b,k,n) smem_f[ WS_OFF + ((((g)*2+(b))*16 + (k))*36) + (n) ]

template<int L>
__device__ void lstm_tile(float* __restrict__ smem_f, int u0,
    const float* __restrict__ ac, const float* __restrict__ Ps,
    const float* __restrict__ h0r, const float* __restrict__ h1r,
    const float* __restrict__ wih, const float* __restrict__ whh,
    const float* __restrict__ b4,
    const float* __restrict__ hprev, float* __restrict__ hout, float* __restrict__ cio)
{
    constexpr int K   = L ? 2048 : 1536;
    constexpr int Kq  = K / 4;
    constexpr int KIH = L ? 1024 : 512;
    constexpr int NT  = Kq / 16;

    const int t = threadIdx.x;
    const int la_m = t >> 2, la_k = (t & 3) << 2;
    const int wg = t >> 6, t6 = t & 63;
    const int lw_n = t6 >> 1, lw_k = (t6 & 1) << 3;
    const int grow = (lw_n & 3) * 1024 + u0 + (lw_n >> 2);
    const float* wih_row = wih + (size_t)grow * KIH;
    const float* whh_row = whh + (size_t)grow * 1024;
    const int ty = t6 >> 2, tx = t6 & 3;

    auto ldA = [&](int kabs) -> float4 {
        if (L == 0) {
            if (kabs < 256)  return *reinterpret_cast<const float4*>(ac  + la_m * 256 + kabs);
            if (kabs < 512)  return *reinterpret_cast<const float4*>(Ps  + la_m * 256 + (kabs - 256));
            return *reinterpret_cast<const float4*>(h0r + la_m * 1024 + (kabs - 512));
        } else {
            if (kabs < 1024) return *reinterpret_cast<const float4*>(h0r + la_m * 1024 + kabs);
            return *reinterpret_cast<const float4*>(h1r + la_m * 1024 + (kabs - 1024));
        }
    };
    auto ldW = [&](int kabs) -> float4 {
        return (kabs < KIH) ? *reinterpret_cast<const float4*>(wih_row + kabs)
                            : *reinterpret_cast<const float4*>(whh_row + (kabs - KIH));
    };

    float4 aR[4], wR0, wR1;
    #pragma unroll
    for (int j = 0; j < 4; j++) aR[j] = ldA(j * Kq + la_k);
    wR0 = ldW(wg * Kq + lw_k);
    wR1 = ldW(wg * Kq + lw_k + 4);
    #pragma unroll
    for (int j = 0; j < 4; j++) {
        ASR(j,0,la_k+0,la_m) = aR[j].x; ASR(j,0,la_k+1,la_m) = aR[j].y;
        ASR(j,0,la_k+2,la_m) = aR[j].z; ASR(j,0,la_k+3,la_m) = aR[j].w;
    }
    WSR(wg,0,lw_k+0,lw_n)=wR0.x; WSR(wg,0,lw_k+1,lw_n)=wR0.y;
    WSR(wg,0,lw_k+2,lw_n)=wR0.z; WSR(wg,0,lw_k+3,lw_n)=wR0.w;
    WSR(wg,0,lw_k+4,lw_n)=wR1.x; WSR(wg,0,lw_k+5,lw_n)=wR1.y;
    WSR(wg,0,lw_k+6,lw_n)=wR1.z; WSR(wg,0,lw_k+7,lw_n)=wR1.w;
    __syncthreads();

    unsigned long long acc[4][4];
    #pragma unroll
    for (int m = 0; m < 4; m++)
        #pragma unroll
        for (int p = 0; p < 4; p++) acc[m][p] = 0ull;

    for (int i = 0; i < NT; i++) {
        int buf = i & 1;
        bool more = (i + 1 < NT);
        if (more) {
            int kb = (i + 1) * 16;
            #pragma unroll
            for (int j = 0; j < 4; j++) aR[j] = ldA(j * Kq + kb + la_k);
            wR0 = ldW(wg * Kq + kb + lw_k);
            wR1 = ldW(wg * Kq + kb + lw_k + 4);
        }
        #pragma unroll
        for (int k = 0; k < 16; k++) {
            float4 a = *reinterpret_cast<const float4*>(&ASR(wg, buf, k, ty << 2));
            F4U b0, b1;
            b0.f = *reinterpret_cast<const float4*>(&WSR(wg, buf, k, tx << 3));
            b1.f = *reinterpret_cast<const float4*>(&WSR(wg, buf, k, (tx << 3) + 4));
            unsigned long long d;
            d = dupf(a.x);
            fma2(acc[0][0], d, b0.u[0]); fma2(acc[0][1], d, b0.u[1]);
            fma2(acc[0][2], d, b1.u[0]); fma2(acc[0][3], d, b1.u[1]);
            d = dupf(a.y);
            fma2(acc[1][0], d, b0.u[0]); fma2(acc[1][1], d, b0.u[1]);
            fma2(acc[1][2], d, b1.u[0]); fma2(acc[1][3], d, b1.u[1]);
            d = dupf(a.z);
            fma2(acc[2][0], d, b0.u[0]); fma2(acc[2][1], d, b0.u[1]);
            fma2(acc[2][2], d, b1.u[0]); fma2(acc[2][3], d, b1.u[1]);
            d = dupf(a.w);
            fma2(acc[3][0], d, b0.u[0]); fma2(acc[3][1], d, b0.u[1]);
            fma2(acc[3][2], d, b1.u[0]); fma2(acc[3][3], d, b1.u[1]);
        }
        if (more) {
            int nb = buf ^ 1;
            #pragma unroll
            for (int j = 0; j < 4; j++) {
                ASR(j,nb,la_k+0,la_m) = aR[j].x; ASR(j,nb,la_k+1,la_m) = aR[j].y;
                ASR(j,nb,la_k+2,la_m) = aR[j].z; ASR(j,nb,la_k+3,la_m) = aR[j].w;
            }
            WSR(wg,nb,lw_k+0,lw_n)=wR0.x; WSR(wg,nb,lw_k+1,lw_n)=wR0.y;
            WSR(wg,nb,lw_k+2,lw_n)=wR0.z; WSR(wg,nb,lw_k+3,lw_n)=wR0.w;
            WSR(wg,nb,lw_k+4,lw_n)=wR1.x; WSR(wg,nb,lw_k+5,lw_n)=wR1.y;
            WSR(wg,nb,lw_k+6,lw_n)=wR1.z; WSR(wg,nb,lw_k+7,lw_n)=wR1.w;
        }
        __syncthreads();
    }

    // cross-group reduction into group 0
    unsigned long long* red = reinterpret_cast<unsigned long long*>(smem_f);
    if (wg > 0) {
        unsigned long long* dst = red + ((size_t)((wg - 1) * 64 + t6)) * 16;
        #pragma unroll
        for (int q = 0; q < 16; q++) dst[q] = acc[q >> 2][q & 3];
    }
    __syncthreads();
    if (wg == 0) {
        #pragma unroll
        for (int r = 0; r < 3; r++) {
            unsigned long long* src = red + ((size_t)(r * 64 + t6)) * 16;
            #pragma unroll
            for (int q = 0; q < 16; q++) add2(acc[q >> 2][q & 3], src[q]);
        }
        // inline pointwise + zoneout: thread owns 4 batches x 2 hidden units
        #pragma unroll
        for (int m = 0; m < 4; m++) {
            int b = (ty << 2) + m;
            #pragma unroll
            for (int hh = 0; hh < 2; hh++) {
                int u = u0 + (tx << 1) + hh;
                float2 p01 = unp(acc[m][2 * hh]);
                float2 p23 = unp(acc[m][2 * hh + 1]);
                float gi = p01.x + b4[u];
                float gf = p01.y + b4[1024 + u];
                float gg = p23.x + b4[2048 + u];
                float go = p23.y + b4[3072 + u];
                int idx = b * 1024 + u;
                float cold = cio[idx], hold = hprev[idx];
                float si = 1.f / (1.f + __expf(-gi));
                float sf = 1.f / (1.f + __expf(-gf));
                float so = 1.f / (1.f + __expf(-go));
                float c2 = sf * cold + si * tanhf(gg);
                float h2 = so * tanhf(c2);
                hout[idx] = 0.1f * hold + 0.9f * h2;
                cio[idx]  = 0.1f * cold + 0.9f * c2;
            }
        }
    }
    __syncthreads();
}

// ---------------- attention (validated math, device-fn form) ----------------
__device__ void att_step(float* __restrict__ smem_f, int s, int b,
    const float* __restrict__ enc, const int* __restrict__ text_len,
    const float* __restrict__ wdec, const float* __restrict__ watt,
    const float* __restrict__ watt_b,
    const float* __restrict__ h0cur, float* __restrict__ ac_out,
    float* __restrict__ attw_out)
{
    float* sWck = smem_f;               // 4224
    float* apad = smem_f + 4224;        // 232
    float* dp   = smem_f + 4456;        // 128
    float* w_s  = smem_f + 4584;        // 128
    float* sE   = smem_f + 4712;        // 200
    float* red  = smem_f + 4912;        // 16
    int tid = threadIdx.x, lane = tid & 31, wid = tid >> 5;
    int len = text_len[b];

    for (int i = tid; i < HATT * 33; i += THR) {
        int h = i / 33, k = i - h * 33;
        sWck[i] = (k < 31) ? g_Wck[h * 32 + k] : 0.f;
    }
    if (tid < 16)  apad[tid] = 0.f;
    if (tid < 17)  apad[215 + tid] = 0.f;
    if (tid < 200) {
        float v = (s == 0) ? ((tid < len) ? 1.f / (float)len : 0.f) : g_acc[b * TE + tid];
        apad[PADC + tid] = v;
    }
    if (tid < HATT) w_s[tid] = watt[tid];

    {
        const float* hr = h0cur + b * DECD;
        for (int h = wid; h < HATT; h += 8) {
            const float* wr = wdec + (size_t)h * DECD;
            float p = 0.f;
            #pragma unroll 8
            for (int j = lane; j < DECD; j += 32) p += wr[j] * hr[j];
            #pragma unroll
            for (int o = 16; o; o >>= 1) p += __shfl_xor_sync(0xffffffffu, p, o);
            if (lane == 0) dp[h] = p;
        }
    }
    __syncthreads();

    const float wb0 = watt_b[0];
    for (int it = 0; it < 25; it++) {
        int t = it * 8 + wid;
        const float* pmrow = g_pm + ((size_t)(b * TE + t)) * HATT;
        float esum = 0.f;
        #pragma unroll
        for (int hh = 0; hh < 4; hh++) {
            int h = lane + (hh << 5);
            const float* wc = sWck + h * 33;
            float conv = 0.f;
            #pragma unroll
            for (int k = 0; k < 31; k++) conv += wc[k] * apad[t + k];
            float x = conv + dp[h] + pmrow[h];
            float ez = __expf(2.f * x);
            float th = 1.f - __fdividef(2.f, ez + 1.f);
            esum += w_s[h] * th;
        }
        #pragma unroll
        for (int o = 16; o; o >>= 1) esum += __shfl_xor_sync(0xffffffffu, esum, o);
        if (lane == 0) sE[t] = esum + wb0;
    }
    __syncthreads();

    float e = (tid < len) ? sE[tid] : -1e30f;
    float mx = e;
    #pragma unroll
    for (int o = 16; o; o >>= 1) mx = fmaxf(mx, __shfl_xor_sync(0xffffffffu, mx, o));
    if (lane == 0) red[wid] = mx;
    __syncthreads();
    if (tid == 0) {
        float mm = red[0];
        for (int i = 1; i < 8; i++) mm = fmaxf(mm, red[i]);
        red[8] = mm;
    }
    __syncthreads();
    mx = red[8];
    float ex = __expf(e - mx);
    float sm = ex;
    #pragma unroll
    for (int o = 16; o; o >>= 1) sm += __shfl_xor_sync(0xffffffffu, sm, o);
    if (lane == 0) red[wid] = sm;
    __syncthreads();
    if (tid == 0) {
        float ss = 0.f;
        for (int i = 0; i < 8; i++) ss += red[i];
        red[9] = ss;
    }
    __syncthreads();
    float inv = 1.f / red[9];
    __syncthreads();
    if (tid < 200) {
        float aw = ex * inv;
        sE[tid] = aw;
        attw_out[((size_t)b * SSTEPS + s) * TE + tid] = aw;
        float an = (s == 0) ? aw : g_acc[b * TE + tid] + aw;
        g_acc[b * TE + tid] = an;
    }
    __syncthreads();

    {
        int c = tid;
        const float* er = enc + ((size_t)b * TE) * ENCD + c;
        float a0 = 0.f, a1 = 0.f, a2 = 0.f, a3 = 0.f;
        #pragma unroll 4
        for (int t = 0; t < TE; t += 4) {
            a0 += sE[t]     * er[(size_t)t * ENCD];
            a1 += sE[t + 1] * er[(size_t)(t + 1) * ENCD];
            a2 += sE[t + 2] * er[(size_t)(t + 2) * ENCD];
            a3 += sE[t + 3] * er[(size_t)(t + 3) * ENCD];
        }
        ac_out[b * ENCD + c] = (a0 + a1) + (a2 + a3);
    }
    __syncthreads();
}

// ---------------- output projection ----------------
__device__ void outproj(float* __restrict__ smem_f, int s, int b,
    const float* __restrict__ h1cur, const float* __restrict__ acbuf,
    const float* __restrict__ fw, const float* __restrict__ pwm,
    const float* __restrict__ pb, float* __restrict__ out)
{
    float* hcs = smem_f;
    int tid = threadIdx.x, lane = tid & 31, wid = tid >> 5;
    for (int i = tid; i < 1280; i += THR)
        hcs[i] = (i < 1024) ? h1cur[b * DECD + i] : acbuf[b * ENCD + (i - 1024)];
    __syncthreads();
    for (int o = wid; o < 162; o += 8) {
        const float* row = (o < 160) ? (fw + (size_t)o * 1280) : (pwm + (size_t)(o - 160) * 1280);
        float sum = 0.f;
        #pragma unroll 4
        for (int i = lane; i < 1280; i += 32) sum += hcs[i] * row[i];
        #pragma unroll
        for (int of = 16; of; of >>= 1) sum += __shfl_xor_sync(0xffffffffu, sum, of);
        if (lane == 0) {
            if (o < 160) {
                int r = o / NC, ch = o % NC;
                out[(size_t)b * NC * TFEAT + (size_t)ch * TFEAT + s * 2 + r] = sum;
            } else {
                out[LOGIT_OFF + (size_t)b * TFEAT + s * 2 + (o - 160)] = sum + pb[o - 160];
            }
        }
    }
    __syncthreads();
}

// ---------------- persistent decoder ----------------
__global__ void __launch_bounds__(THR, 1) k_decoder(
    const float* __restrict__ enc, const int* __restrict__ tlen,
    const float* __restrict__ wdec, const float* __restrict__ watt,
    const float* __restrict__ wattb,
    const float* __restrict__ l0wih, const float* __restrict__ l0whh,
    const float* __restrict__ l1wih, const float* __restrict__ l1whh,
    const float* __restrict__ fow, const float* __restrict__ pow_,
    const float* __restrict__ pob, float* __restrict__ out)
{
    extern __shared__ float smem_f[];
    int blk = blockIdx.x;
    unsigned gen = 0;
    float* attw = out + ATTW_OFF;

    // P0: attention for step 0 (h0 = 0, uniform prior)
    if (blk < 64)
        att_step(smem_f, 0, blk, enc, tlen, wdec, watt, wattb, g_h0, g_ac4, attw);
    gen++; gbar(gen * GRID);

    for (int s = 0; s < SSTEPS; s++) {
        int p = s & 1;
        const float* Ps = g_P + (size_t)s * NB * PRE;
        // P2: lstm0 (all 128 blocks)
        lstm_tile<0>(smem_f, blk * 8,
                     g_ac4 + (size_t)(s & 3) * NB * ENCD, Ps,
                     g_h0 + (size_t)p * HSZ, nullptr,
                     l0wih, l0whh, g_b40,
                     g_h0 + (size_t)p * HSZ, g_h0 + (size_t)(p ^ 1) * HSZ, g_c0);
        gen++; gbar(gen * GRID);
        // P3: lstm1 (all) || att(s+1) on blocks 0-63 || outproj(s-1) on blocks 64-127
        lstm_tile<1>(smem_f, blk * 8,
                     nullptr, nullptr,
                     g_h0 + (size_t)(p ^ 1) * HSZ, g_h1 + (size_t)p * HSZ,
                     l1wih, l1whh, g_b41,
                     g_h1 + (size_t)p * HSZ, g_h1 + (size_t)(p ^ 1) * HSZ, g_c1);
        if (blk < 64) {
            if (s + 1 < SSTEPS)
                att_step(smem_f, s + 1, blk, enc, tlen, wdec, watt, wattb,
                         g_h0 + (size_t)(p ^ 1) * HSZ,
                         g_ac4 + (size_t)((s + 1) & 3) * NB * ENCD, attw);
        } else {
            if (s >= 1)
                outproj(smem_f, s - 1, blk - 64,
                        g_h1 + (size_t)(s & 1) * HSZ,
                        g_ac4 + (size_t)((s - 1) & 3) * NB * ENCD,
                        fow, pow_, pob, out);
        }
        gen++; gbar(gen * GRID);
    }
    // tail: outproj for the last step
    if (blk < 64)
        outproj(smem_f, SSTEPS - 1, blk,
                g_h1 + (size_t)(SSTEPS & 1) * HSZ,
                g_ac4 + (size_t)((SSTEPS - 1) & 3) * NB * ENCD,
                fow, pow_, pob, out);
}

// ---------------- host ----------------
static float* symaddr(const void* sym) {
    void* p = nullptr;
    cudaGetSymbolAddress(&p, sym);
    return (float*)p;
}

extern "C" void kernel_launch(void* const* d_in, const int* in_sizes, int n_in,
                              void* d_out, int out_size)
{
    const float* enc    = (const float*)d_in[0];
    const int*   tlen   = (const int*)  d_in[1];
    const float* ft     = (const float*)d_in[2];
    const float* enc_w  = (const float*)d_in[3];
    const float* enc_b  = (const float*)d_in[4];
    const float* dec_w  = (const float*)d_in[5];
    const float* att_w  = (const float*)d_in[6];
    const float* conv_w = (const float*)d_in[7];
    const float* ww     = (const float*)d_in[8];
    const float* wbb    = (const float*)d_in[9];
    const float* pw0    = (const float*)d_in[10];
    const float* pb0    = (const float*)d_in[11];
    const float* pw1    = (const float*)d_in[12];
    const float* pb1    = (const float*)d_in[13];
    const float* l0wih  = (const float*)d_in[14];
    const float* l0whh  = (const float*)d_in[15];
    const float* l0bih  = (const float*)d_in[16];
    const float* l0bhh  = (const float*)d_in[17];
    const float* l1wih  = (const float*)d_in[18];
    const float* l1whh  = (const float*)d_in[19];
    const float* l1bih  = (const float*)d_in[20];
    const float* l1bhh  = (const float*)d_in[21];
    const float* fow    = (const float*)d_in[22];
    const float* pow_   = (const float*)d_in[23];
    const float* pob    = (const float*)d_in[24];
    float* out = (float*)d_out;

    float* pm_p = symaddr(g_pm);
    float* preH = symaddr(g_preH);
    float* Pp   = symaddr(g_P);

    static int smem_set = 0;
    if (!smem_set) {
        cudaFuncSetAttribute(k_decoder, cudaFuncAttributeMaxDynamicSharedMemorySize,
                             SMEM_FLOATS * 4);
        smem_set = 1;
    }

    // setup (6 graph nodes total)
    k_wck<<<16, 256>>>(att_w, conv_w);
    k_init<<<(2 * HSZ + 255) / 256, 256>>>(l0bih, l0bhh, l1bih, l1bhh);
    k_gemm<0><<<dim3(200, 2), 256>>>(enc, enc_w, enc_b, pm_p, 128, 256, 256, nullptr, 0);
    k_gemm<1><<<dim3(500, 4), 256>>>(nullptr, pw0, pb0, preH, 256, 160, 0, ft, 1);
    k_gemm<0><<<dim3(500, 4), 256>>>(preH, pw1, pb1, Pp, 256, 256, 256, nullptr, 1);

    k_decoder<<<GRID, THR, SMEM_FLOATS * 4>>>(
        enc, tlen, dec_w, ww, wbb,
        l0wih, l0whh, l1wih, l1whh,
        fow, pow_, pob, out);
}

// round 9
// speedup vs baseline: 1.4094x; 1.3596x over previous
#include <cuda_runtime.h>
#include <cuda_bf16.h>
#include <cstdint>

#define NB    64
#define TE    200
#define ENCD  256
#define DECD  1024
#define HATT  128
#define NCONV 32
#define KCONV 31
#define PADC  15
#define PRE   256
#define NC    80
#define TFEAT 1000
#define SSTEPS 500
#define HSZ   (NB*DECD)

#define LOGIT_OFF 5120000
#define ATTW_OFF  5184000

#define GRID  128
#define THR   512

// dynamic smem (bytes): double-buffered W(hi/lo) 128x64 bf16 + act(hi/lo) 64x64 bf16
#define SM_AWH(b)  (1024  + (b)*16384)
#define SM_AWL(b)  (33792 + (b)*16384)
#define SM_BXH(b)  (66560 + (b)*8192)
#define SM_BXL(b)  (82944 + (b)*8192)
#define SM_TOTAL   99328
#define SM_F_OFF   256      // float index of att/outproj scratch (byte 1024)

// ---------------- scratch ----------------
__device__ float g_pm[NB*TE*HATT];
__device__ float g_Wck[HATT*32];
__device__ float g_preH[SSTEPS*NB*PRE];
__device__ float g_P[SSTEPS*NB*PRE];
__device__ __nv_bfloat16 g_Ph[SSTEPS*NB*PRE], g_Pl[SSTEPS*NB*PRE];
__device__ __nv_bfloat16 g_W0h[4096*1536], g_W0l[4096*1536];
__device__ __nv_bfloat16 g_W1h[4096*2048], g_W1l[4096*2048];
__device__ float g_part[4*4096*64];      // [kq][row][batch]
__device__ float g_acf[2*NB*ENCD];
__device__ __nv_bfloat16 g_ach[NB*ENCD], g_acl[NB*ENCD];
__device__ float g_h0f[HSZ], g_c0[HSZ];
__device__ float g_h1f[HSZ], g_c1[HSZ];
__device__ __nv_bfloat16 g_h0h[HSZ], g_h0l[HSZ], g_h1h[HSZ], g_h1l[HSZ];
__device__ float g_acc[NB*TE];
__device__ float g_b40[4096], g_b41[4096];
__device__ unsigned g_bar;

// ---------------- warp MMA helpers (portable sm_80+, OK on sm_103 non-a) -------
__device__ __forceinline__ uint32_t smem_u32_of(const void* p) {
    uint32_t a;
    asm("{ .reg .u64 t; cvta.to.shared.u64 t, %1; cvt.u32.u64 %0, t; }" : "=r"(a) : "l"(p));
    return a;
}
__device__ __forceinline__ void ldsm4(uint32_t* r, uint32_t addr) {
    asm volatile("ldmatrix.sync.aligned.m8n8.x4.shared.b16 {%0,%1,%2,%3}, [%4];"
        : "=r"(r[0]), "=r"(r[1]), "=r"(r[2]), "=r"(r[3]) : "r"(addr));
}
__device__ __forceinline__ void mma16816(float* c, const uint32_t* a, uint32_t b0, uint32_t b1) {
    asm volatile("mma.sync.aligned.m16n8k16.row.col.f32.bf16.bf16.f32 "
        "{%0,%1,%2,%3}, {%4,%5,%6,%7}, {%8,%9}, {%0,%1,%2,%3};"
        : "+f"(c[0]), "+f"(c[1]), "+f"(c[2]), "+f"(c[3])
        : "r"(a[0]), "r"(a[1]), "r"(a[2]), "r"(a[3]), "r"(b0), "r"(b1));
}

// ---------------- grid barrier (validated) ----------------
__device__ __forceinline__ void gbar(unsigned target) {
    __syncthreads();
    if (threadIdx.x == 0) {
        __threadfence();
        atomicAdd(&g_bar, 1u);
        while (*(volatile unsigned*)&g_bar < target) { }
        __threadfence();
    }
    __syncthreads();
}

// ---------------- setup kernels ----------------
__global__ void k_wck(const float* __restrict__ watt, const float* __restrict__ cw) {
    int idx = blockIdx.x * blockDim.x + threadIdx.x;
    if (idx >= HATT * 32) return;
    int h = idx >> 5, k = idx & 31;
    float s = 0.f;
    if (k < KCONV) {
        #pragma unroll
        for (int c = 0; c < NCONV; c++) s += watt[h * NCONV + c] * cw[c * KCONV + k];
    }
    g_Wck[idx] = s;
}

__global__ void k_init(const float* __restrict__ b0a, const float* __restrict__ b0b,
                       const float* __restrict__ b1a, const float* __restrict__ b1b) {
    int i = blockIdx.x * blockDim.x + threadIdx.x;
    if (i == 0) g_bar = 0u;
    if (i < HSZ) {
        g_h0f[i] = 0.f; g_h1f[i] = 0.f; g_c0[i] = 0.f; g_c1[i] = 0.f;
        __nv_bfloat16 z = __float2bfloat16(0.f);
        g_h0h[i] = z; g_h0l[i] = z; g_h1h[i] = z; g_h1l[i] = z;
    }
    if (i < 4096) { g_b40[i] = b0a[i] + b0b[i]; g_b41[i] = b1a[i] + b1b[i]; }
}

__global__ void k_cvtW(const float* __restrict__ wih, const float* __restrict__ whh,
                       int KIH, int KT, __nv_bfloat16* __restrict__ Wh,
                       __nv_bfloat16* __restrict__ Wl, int total) {
    int idx = blockIdx.x * blockDim.x + threadIdx.x;
    if (idx >= total) return;
    int r = idx / KT, k = idx - r * KT;
    float v = (k < KIH) ? wih[(size_t)r * KIH + k] : whh[(size_t)r * 1024 + (k - KIH)];
    __nv_bfloat16 hi = __float2bfloat16(v);
    Wh[idx] = hi;
    Wl[idx] = __float2bfloat16(v - __bfloat162float(hi));
}

__global__ void k_cvtP() {
    int idx = blockIdx.x * blockDim.x + threadIdx.x;
    if (idx >= SSTEPS * NB * PRE) return;
    float v = g_P[idx];
    __nv_bfloat16 hi = __float2bfloat16(v);
    g_Ph[idx] = hi;
    g_Pl[idx] = __float2bfloat16(v - __bfloat162float(hi));
}

// ---------------- setup GEMM (validated):  C = A*W^T (+bias, relu) -------------
template<int LOADER>
__global__ __launch_bounds__(256) void k_gemm(
    const float* __restrict__ A, const float* __restrict__ W,
    const float* __restrict__ bias, float* __restrict__ Cout,
    int N, int K, int lda, const float* __restrict__ ft, int relu)
{
    __shared__ float As[16][68];
    __shared__ float Ws[16][68];
    int tid  = threadIdx.x;
    int mb = blockIdx.x * 64, nb = blockIdx.y * 64;
    int la_m = tid >> 2, la_k = (tid & 3) << 2;
    int tx = tid & 15, ty = tid >> 4;
    float acc[4][4] = {};

    for (int k0 = 0; k0 < K; k0 += 16) {
        float4 av;
        if (LOADER == 0) {
            av = *reinterpret_cast<const float4*>(A + (size_t)(mb + la_m) * lda + k0 + la_k);
        } else {
            int row = mb + la_m;
            int s = row >> 6, bb = row & 63;
            float t0 = 0.f, t1 = 0.f, t2 = 0.f, t3 = 0.f;
            if (s > 0) {
                int base = (s - 1) * 2;
                int k = k0 + la_k;
                const float* fb = ft + (size_t)bb * NC * TFEAT;
                t0 = fb[(k % NC) * TFEAT + base + k / NC]; k++;
                t1 = fb[(k % NC) * TFEAT + base + k / NC]; k++;
                t2 = fb[(k % NC) * TFEAT + base + k / NC]; k++;
                t3 = fb[(k % NC) * TFEAT + base + k / NC];
            }
            av = make_float4(t0, t1, t2, t3);
        }
        As[la_k][la_m] = av.x; As[la_k+1][la_m] = av.y;
        As[la_k+2][la_m] = av.z; As[la_k+3][la_m] = av.w;
        float4 wv = *reinterpret_cast<const float4*>(W + (size_t)(nb + la_m) * K + k0 + la_k);
        Ws[la_k][la_m] = wv.x; Ws[la_k+1][la_m] = wv.y;
        Ws[la_k+2][la_m] = wv.z; Ws[la_k+3][la_m] = wv.w;
        __syncthreads();
        #pragma unroll
        for (int k = 0; k < 16; k++) {
            float4 a = *reinterpret_cast<const float4*>(&As[k][ty << 2]);
            float4 b = *reinterpret_cast<const float4*>(&Ws[k][tx << 2]);
            acc[0][0] += a.x*b.x; acc[0][1] += a.x*b.y; acc[0][2] += a.x*b.z; acc[0][3] += a.x*b.w;
            acc[1][0] += a.y*b.x; acc[1][1] += a.y*b.y; acc[1][2] += a.y*b.z; acc[1][3] += a.y*b.w;
            acc[2][0] += a.z*b.x; acc[2][1] += a.z*b.y; acc[2][2] += a.z*b.z; acc[2][3] += a.z*b.w;
            acc[3][0] += a.w*b.x; acc[3][1] += a.w*b.y; acc[3][2] += a.w*b.z; acc[3][3] += a.w*b.w;
        }
        __syncthreads();
    }
    #pragma unroll
    for (int i = 0; i < 4; i++) {
        int m = mb + (ty << 2) + i;
        #pragma unroll
        for (int j = 0; j < 4; j++) {
            int n = nb + (tx << 2) + j;
            float v = acc[i][j] + bias[n];
            if (relu) v = fmaxf(v, 0.f);
            Cout[(size_t)m * N + n] = v;
        }
    }
}

// ---------------- GEMM-phase chunk load/store (validated layout) ----------------
struct Regs6 { uint4 v[6]; };

__device__ __forceinline__ void ldg_chunk(Regs6& R,
    const __nv_bfloat16* __restrict__ Wh, const __nv_bfloat16* __restrict__ Wl,
    const __nv_bfloat16* __restrict__ Bh, const __nv_bfloat16* __restrict__ Bl,
    int bstr, int KT, int rowbase, int k0, int koff, int tid)
{
    #pragma unroll
    for (int j = 0; j < 2; j++) {
        int seg = tid + j * 512;
        int r = seg >> 3, cs = seg & 7;
        size_t off = (size_t)(rowbase + r) * KT + k0 + cs * 8;
        R.v[j]     = *reinterpret_cast<const uint4*>(Wh + off);
        R.v[2 + j] = *reinterpret_cast<const uint4*>(Wl + off);
    }
    {
        int r = tid >> 3, cs = tid & 7;
        size_t off = (size_t)r * bstr + koff + cs * 8;
        R.v[4] = *reinterpret_cast<const uint4*>(Bh + off);
        R.v[5] = *reinterpret_cast<const uint4*>(Bl + off);
    }
}

__device__ __forceinline__ void sts_chunk(const Regs6& R, char* sm, int buf, int tid) {
    #pragma unroll
    for (int j = 0; j < 2; j++) {
        int seg = tid + j * 512;
        int r = seg >> 3, cs = seg & 7;
        uint32_t off = r * 128 + cs * 16;
        uint32_t sw = off ^ ((off >> 3) & 0x70);
        *reinterpret_cast<uint4*>(sm + SM_AWH(buf) + sw) = R.v[j];
        *reinterpret_cast<uint4*>(sm + SM_AWL(buf) + sw) = R.v[2 + j];
    }
    {
        int r = tid >> 3, cs = tid & 7;
        uint32_t off = r * 128 + cs * 16;
        uint32_t sw = off ^ ((off >> 3) & 0x70);
        *reinterpret_cast<uint4*>(sm + SM_BXH(buf) + sw) = R.v[4];
        *reinterpret_cast<uint4*>(sm + SM_BXL(buf) + sw) = R.v[5];
    }
}

// ---------------- one LSTM GEMM phase via mma.sync (bf16 3-term split) ---------
// Block computes gates[rowbase..rowbase+128) x batch(64) over K-quarter kq.
// 16 warps: warp w -> rows [w/2*16, +16), cols [(w&1)*32, +32).
template<int L>
__device__ void gemm_phase(char* sm, uint32_t smb, int rb, int kq, int s,
    const __nv_bfloat16* __restrict__ Wh, const __nv_bfloat16* __restrict__ Wl,
    int tid)
{
    constexpr int KT = L ? 2048 : 1536;
    constexpr int NCH = L ? 8 : 6;
    const int rowbase = rb * 128;
    const int kqbase = kq * (KT / 4);

    const int warp = tid >> 5, lane = tid & 31;
    const int mt = warp >> 1;            // 0..7
    const int nh = (warp & 1) * 32;      // 0 or 32

    // ldmatrix lane geometry (constant over chunks)
    const int ar = mt * 16 + (lane & 15);
    const uint32_t aoff0 = (uint32_t)ar * 128 + (uint32_t)(lane >> 4) * 16;
    const uint32_t amx = (uint32_t)(ar & 7) << 4;
    const int bn0 = nh + ((lane >> 4) & 1) * 8 + (lane & 7);
    const uint32_t boff0 = (uint32_t)bn0 * 128 + (uint32_t)((lane >> 3) & 1) * 16;
    const uint32_t bmx = (uint32_t)(bn0 & 7) << 4;

    auto resolveB = [&](int k0, const __nv_bfloat16*& bh, const __nv_bfloat16*& bl,
                        int& bstr, int& koff) {
        if (L == 0) {
            if (k0 < 256)      { bh = g_ach; bl = g_acl; bstr = 256; koff = k0; }
            else if (k0 < 512) { bh = g_Ph + (size_t)s * NB * PRE;
                                 bl = g_Pl + (size_t)s * NB * PRE; bstr = 256; koff = k0 - 256; }
            else               { bh = g_h0h; bl = g_h0l; bstr = 1024; koff = k0 - 512; }
        } else {
            bstr = 1024;
            if (k0 < 1024) { bh = g_h0h; bl = g_h0l; koff = k0; }
            else           { bh = g_h1h; bl = g_h1l; koff = k0 - 1024; }
        }
    };

    float acc[4][4];
    #pragma unroll
    for (int nt = 0; nt < 4; nt++)
        #pragma unroll
        for (int q = 0; q < 4; q++) acc[nt][q] = 0.f;

    {   // prologue: chunk 0 -> buf 0
        Regs6 R; const __nv_bfloat16 *bh, *bl; int bstr, koff;
        resolveB(kqbase, bh, bl, bstr, koff);
        ldg_chunk(R, Wh, Wl, bh, bl, bstr, KT, rowbase, kqbase, koff, tid);
        sts_chunk(R, sm, 0, tid);
    }
    __syncthreads();

    for (int i = 0; i < NCH; i++) {
        Regs6 R;
        const int buf = i & 1;
        const bool more = (i + 1 < NCH);
        if (more) {
            int k0 = kqbase + (i + 1) * 64;
            const __nv_bfloat16 *bh, *bl; int bstr, koff;
            resolveB(k0, bh, bl, bstr, koff);
            ldg_chunk(R, Wh, Wl, bh, bl, bstr, KT, rowbase, k0, koff, tid);
        }
        const uint32_t awh = smb + SM_AWH(buf), awl = smb + SM_AWL(buf);
        const uint32_t bxh = smb + SM_BXH(buf), bxl = smb + SM_BXL(buf);
        #pragma unroll
        for (int kk = 0; kk < 4; kk++) {
            const uint32_t col = kk * 32;
            uint32_t ah[4], al[4], bh0[4], bh1[4], bl0[4], bl1[4];
            const uint32_t aof = (aoff0 + col) ^ amx;
            ldsm4(ah, awh + aof);
            ldsm4(al, awl + aof);
            const uint32_t bof = (boff0 + col) ^ bmx;
            ldsm4(bh0, bxh + bof);
            ldsm4(bh1, bxh + bof + 2048);
            ldsm4(bl0, bxl + bof);
            ldsm4(bl1, bxl + bof + 2048);
            // 4 n-tiles: (bh0[0],bh0[1]) (bh0[2],bh0[3]) (bh1[0],bh1[1]) (bh1[2],bh1[3])
            mma16816(acc[0], ah, bh0[0], bh0[1]);
            mma16816(acc[1], ah, bh0[2], bh0[3]);
            mma16816(acc[2], ah, bh1[0], bh1[1]);
            mma16816(acc[3], ah, bh1[2], bh1[3]);
            mma16816(acc[0], ah, bl0[0], bl0[1]);
            mma16816(acc[1], ah, bl0[2], bl0[3]);
            mma16816(acc[2], ah, bl1[0], bl1[1]);
            mma16816(acc[3], ah, bl1[2], bl1[3]);
            mma16816(acc[0], al, bh0[0], bh0[1]);
            mma16816(acc[1], al, bh0[2], bh0[3]);
            mma16816(acc[2], al, bh1[0], bh1[1]);
            mma16816(acc[3], al, bh1[2], bh1[3]);
        }
        __syncthreads();
        if (more) {
            sts_chunk(R, sm, buf ^ 1, tid);
            __syncthreads();
        }
    }

    // epilogue: write fp32 partials
    {
        const int trow = lane >> 2, tcol = (lane & 3) * 2;
        #pragma unroll
        for (int nt = 0; nt < 4; nt++) {
            int row = rowbase + mt * 16 + trow;
            int col = nh + nt * 8 + tcol;
            float* dst = g_part + ((size_t)kq * 4096 + row) * 64 + col;
            *reinterpret_cast<float2*>(dst) = make_float2(acc[nt][0], acc[nt][1]);
            *reinterpret_cast<float2*>(dst + 8 * 64) = make_float2(acc[nt][2], acc[nt][3]);
        }
    }
}

// ---------------- pointwise + zoneout + bf16 split ----------------
__device__ void pw_phase(int u0, const float* __restrict__ b4,
    float* __restrict__ hf, __nv_bfloat16* __restrict__ hh, __nv_bfloat16* __restrict__ hl,
    float* __restrict__ cf, int tid)
{
    int ul = tid >> 6, bat = tid & 63;
    int u = u0 + ul;
    float g[4];
    #pragma unroll
    for (int gg = 0; gg < 4; gg++) {
        int row = gg * 1024 + u;
        float v = b4[row];
        #pragma unroll
        for (int kq = 0; kq < 4; kq++)
            v += g_part[((size_t)kq * 4096 + row) * 64 + bat];
        g[gg] = v;
    }
    int idx = bat * 1024 + u;
    float cold = cf[idx], hold = hf[idx];
    float si = 1.f / (1.f + __expf(-g[0]));
    float sf = 1.f / (1.f + __expf(-g[1]));
    float so = 1.f / (1.f + __expf(-g[3]));
    float c2 = sf * cold + si * tanhf(g[2]);
    float h2 = so * tanhf(c2);
    float hn = 0.1f * hold + 0.9f * h2;
    float cn = 0.1f * cold + 0.9f * c2;
    hf[idx] = hn; cf[idx] = cn;
    __nv_bfloat16 hi = __float2bfloat16(hn);
    hh[idx] = hi;
    hl[idx] = __float2bfloat16(hn - __bfloat162float(hi));
}

// ---------------- attention (512-thread; validated math) ----------------
__device__ void att_step(float* __restrict__ smf, int s, int b,
    const float* __restrict__ enc, const int* __restrict__ text_len,
    const float* __restrict__ wdec, const float* __restrict__ watt,
    const float* __restrict__ watt_b, float* __restrict__ attw_out)
{
    float* sWck = smf;                  // 4224
    float* apad = smf + 4224;           // 232
    float* dp   = smf + 4456;           // 128
    float* w_s  = smf + 4584;           // 128
    float* sE   = smf + 4712;           // 200
    float* red  = smf + 4912;           // 32
    int tid = threadIdx.x, lane = tid & 31, wid = tid >> 5;
    int len = text_len[b];

    for (int i = tid; i < HATT * 33; i += THR) {
        int h = i / 33, k = i - h * 33;
        sWck[i] = (k < 31) ? g_Wck[h * 32 + k] : 0.f;
    }
    if (tid < 16)  apad[tid] = 0.f;
    if (tid < 17)  apad[215 + tid] = 0.f;
    if (tid < 200) {
        float v = (s == 0) ? ((tid < len) ? 1.f / (float)len : 0.f) : g_acc[b * TE + tid];
        apad[PADC + tid] = v;
    }
    if (tid < HATT) w_s[tid] = watt[tid];

    {
        const float* hr = g_h0f + b * DECD;
        for (int h = wid; h < HATT; h += 16) {
            const float* wr = wdec + (size_t)h * DECD;
            float p = 0.f;
            #pragma unroll 8
            for (int j = lane; j < DECD; j += 32) p += wr[j] * hr[j];
            #pragma unroll
            for (int o = 16; o; o >>= 1) p += __shfl_xor_sync(0xffffffffu, p, o);
            if (lane == 0) dp[h] = p;
        }
    }
    __syncthreads();

    const float wb0 = watt_b[0];
    for (int it = 0; it < 13; it++) {
        int t = it * 16 + wid;
        if (t < TE) {
            const float* pmrow = g_pm + ((size_t)(b * TE + t)) * HATT;
            float esum = 0.f;
            #pragma unroll
            for (int hh = 0; hh < 4; hh++) {
                int h = lane + (hh << 5);
                const float* wc = sWck + h * 33;
                float conv = 0.f;
                #pragma unroll
                for (int k = 0; k < 31; k++) conv += wc[k] * apad[t + k];
                float x = conv + dp[h] + pmrow[h];
                float ez = __expf(2.f * x);
                float th = 1.f - __fdividef(2.f, ez + 1.f);
                esum += w_s[h] * th;
            }
            #pragma unroll
            for (int o = 16; o; o >>= 1) esum += __shfl_xor_sync(0xffffffffu, esum, o);
            if (lane == 0) sE[t] = esum + wb0;
        }
    }
    __syncthreads();

    float e = (tid < len) ? sE[tid] : -1e30f;
    float mx = e;
    #pragma unroll
    for (int o = 16; o; o >>= 1) mx = fmaxf(mx, __shfl_xor_sync(0xffffffffu, mx, o));
    if (lane == 0) red[wid] = mx;
    __syncthreads();
    if (tid == 0) {
        float mm = red[0];
        for (int i = 1; i < 16; i++) mm = fmaxf(mm, red[i]);
        red[16] = mm;
    }
    __syncthreads();
    mx = red[16];
    float ex = (tid < 200) ? __expf(e - mx) : 0.f;
    float sm = ex;
    #pragma unroll
    for (int o = 16; o; o >>= 1) sm += __shfl_xor_sync(0xffffffffu, sm, o);
    if (lane == 0) red[wid] = sm;
    __syncthreads();
    if (tid == 0) {
        float ss = 0.f;
        for (int i = 0; i < 16; i++) ss += red[i];
        red[17] = ss;
    }
    __syncthreads();
    float inv = 1.f / red[17];
    __syncthreads();
    if (tid < 200) {
        float aw = ex * inv;
        sE[tid] = aw;
        attw_out[((size_t)b * SSTEPS + s) * TE + tid] = aw;
        float an = (s == 0) ? aw : g_acc[b * TE + tid] + aw;
        g_acc[b * TE + tid] = an;
    }
    __syncthreads();

    if (tid < ENCD) {
        int c = tid;
        const float* er = enc + ((size_t)b * TE) * ENCD + c;
        float a0 = 0.f, a1 = 0.f, a2 = 0.f, a3 = 0.f;
        #pragma unroll 4
        for (int t = 0; t < TE; t += 4) {
            a0 += sE[t]     * er[(size_t)t * ENCD];
            a1 += sE[t + 1] * er[(size_t)(t + 1) * ENCD];
            a2 += sE[t + 2] * er[(size_t)(t + 2) * ENCD];
            a3 += sE[t + 3] * er[(size_t)(t + 3) * ENCD];
        }
        float ac = (a0 + a1) + (a2 + a3);
        g_acf[(size_t)(s & 1) * NB * ENCD + b * ENCD + c] = ac;
        __nv_bfloat16 hi = __float2bfloat16(ac);
        g_ach[b * ENCD + c] = hi;
        g_acl[b * ENCD + c] = __float2bfloat16(ac - __bfloat162float(hi));
    }
    __syncthreads();
}

// ---------------- output projection (512-thread) ----------------
__device__ void outproj(float* __restrict__ smf, int s, int b,
    const float* __restrict__ fw, const float* __restrict__ pwm,
    const float* __restrict__ pb, float* __restrict__ out)
{
    float* hcs = smf;
    int tid = threadIdx.x, lane = tid & 31, wid = tid >> 5;
    const float* acb = g_acf + (size_t)(s & 1) * NB * ENCD;
    for (int i = tid; i < 1280; i += THR)
        hcs[i] = (i < 1024) ? g_h1f[b * DECD + i] : acb[b * ENCD + (i - 1024)];
    __syncthreads();
    for (int o = wid; o < 162; o += 16) {
        const float* row = (o < 160) ? (fw + (size_t)o * 1280) : (pwm + (size_t)(o - 160) * 1280);
        float sum = 0.f;
        #pragma unroll 4
        for (int i = lane; i < 1280; i += 32) sum += hcs[i] * row[i];
        #pragma unroll
        for (int of = 16; of; of >>= 1) sum += __shfl_xor_sync(0xffffffffu, sum, of);
        if (lane == 0) {
            if (o < 160) {
                int r = o / NC, ch = o % NC;
                out[(size_t)b * NC * TFEAT + (size_t)ch * TFEAT + s * 2 + r] = sum;
            } else {
                out[LOGIT_OFF + (size_t)b * TFEAT + s * 2 + (o - 160)] = sum + pb[o - 160];
            }
        }
    }
    __syncthreads();
}

// ---------------- persistent decoder ----------------
__global__ void __launch_bounds__(THR, 1) k_decoder(
    const float* __restrict__ enc, const int* __restrict__ tlen,
    const float* __restrict__ wdec, const float* __restrict__ watt,
    const float* __restrict__ wattb,
    const float* __restrict__ fow, const float* __restrict__ pow_,
    const float* __restrict__ pob, float* __restrict__ out)
{
    extern __shared__ char sm[];
    float* smf = reinterpret_cast<float*>(sm) + SM_F_OFF;
    uint32_t smb = smem_u32_of(sm);
    int tid = threadIdx.x;
    int blk = blockIdx.x;
    int rb = blk >> 2, kq = blk & 3;
    float* attw = out + ATTW_OFF;
    unsigned gen = 0;

    // phase 0: attention for step 0 (h0 = 0, uniform prior)
    if (blk < 64)
        att_step(smf, 0, blk, enc, tlen, wdec, watt, wattb, attw);
    gen++; gbar(gen * GRID);

    for (int s = 0; s < SSTEPS; s++) {
        // A: lstm0 GEMM
        gemm_phase<0>(sm, smb, rb, kq, s, g_W0h, g_W0l, tid);
        gen++; gbar(gen * GRID);
        // B: pw0 (all) + outproj(s-1) on blocks >= 64
        pw_phase(blk * 8, g_b40, g_h0f, g_h0h, g_h0l, g_c0, tid);
        if (blk >= 64 && s >= 1)
            outproj(smf, s - 1, blk - 64, fow, pow_, pob, out);
        gen++; gbar(gen * GRID);
        // C: lstm1 GEMM
        gemm_phase<1>(sm, smb, rb, kq, s, g_W1h, g_W1l, tid);
        gen++; gbar(gen * GRID);
        // D: pw1 (all) + attention(s+1) on blocks < 64
        pw_phase(blk * 8, g_b41, g_h1f, g_h1h, g_h1l, g_c1, tid);
        if (blk < 64 && s + 1 < SSTEPS)
            att_step(smf, s + 1, blk, enc, tlen, wdec, watt, wattb, attw);
        gen++; gbar(gen * GRID);
    }
    // tail: outproj for the last step
    if (blk >= 64)
        outproj(smf, SSTEPS - 1, blk - 64, fow, pow_, pob, out);
}

// ---------------- host ----------------
static float* symaddr(const void* sym) {
    void* p = nullptr;
    cudaGetSymbolAddress(&p, sym);
    return (float*)p;
}

extern "C" void kernel_launch(void* const* d_in, const int* in_sizes, int n_in,
                              void* d_out, int out_size)
{
    const float* enc    = (const float*)d_in[0];
    const int*   tlen   = (const int*)  d_in[1];
    const float* ft     = (const float*)d_in[2];
    const float* enc_w  = (const float*)d_in[3];
    const float* enc_b  = (const float*)d_in[4];
    const float* dec_w  = (const float*)d_in[5];
    const float* att_w  = (const float*)d_in[6];
    const float* conv_w = (const float*)d_in[7];
    const float* ww     = (const float*)d_in[8];
    const float* wbb    = (const float*)d_in[9];
    const float* pw0    = (const float*)d_in[10];
    const float* pb0    = (const float*)d_in[11];
    const float* pw1    = (const float*)d_in[12];
    const float* pb1    = (const float*)d_in[13];
    const float* l0wih  = (const float*)d_in[14];
    const float* l0whh  = (const float*)d_in[15];
    const float* l0bih  = (const float*)d_in[16];
    const float* l0bhh  = (const float*)d_in[17];
    const float* l1wih  = (const float*)d_in[18];
    const float* l1whh  = (const float*)d_in[19];
    const float* l1bih  = (const float*)d_in[20];
    const float* l1bhh  = (const float*)d_in[21];
    const float* fow    = (const float*)d_in[22];
    const float* pow_   = (const float*)d_in[23];
    const float* pob    = (const float*)d_in[24];
    float* out = (float*)d_out;

    float* pm_p = symaddr(g_pm);
    float* preH = symaddr(g_preH);
    float* Pp   = symaddr(g_P);
    __nv_bfloat16* W0h = (__nv_bfloat16*)symaddr(g_W0h);
    __nv_bfloat16* W0l = (__nv_bfloat16*)symaddr(g_W0l);
    __nv_bfloat16* W1h = (__nv_bfloat16*)symaddr(g_W1h);
    __nv_bfloat16* W1l = (__nv_bfloat16*)symaddr(g_W1l);

    static int smem_set = 0;
    if (!smem_set) {
        cudaFuncSetAttribute(k_decoder, cudaFuncAttributeMaxDynamicSharedMemorySize, SM_TOTAL);
        smem_set = 1;
    }

    k_wck<<<16, 256>>>(att_w, conv_w);
    k_init<<<(HSZ + 255) / 256, 256>>>(l0bih, l0bhh, l1bih, l1bhh);
    k_gemm<0><<<dim3(200, 2), 256>>>(enc, enc_w, enc_b, pm_p, 128, 256, 256, nullptr, 0);
    k_gemm<1><<<dim3(500, 4), 256>>>(nullptr, pw0, pb0, preH, 256, 160, 0, ft, 1);
    k_gemm<0><<<dim3(500, 4), 256>>>(preH, pw1, pb1, Pp, 256, 256, 256, nullptr, 1);
    k_cvtW<<<(4096 * 1536 + 255) / 256, 256>>>(l0wih, l0whh, 512, 1536, W0h, W0l, 4096 * 1536);
    k_cvtW<<<(4096 * 2048 + 255) / 256, 256>>>(l1wih, l1whh, 1024, 2048, W1h, W1l, 4096 * 2048);
    k_cvtP<<<(SSTEPS * NB * PRE + 255) / 256, 256>>>();

    k_decoder<<<GRID, THR, SM_TOTAL>>>(
        enc, tlen, dec_w, ww, wbb, fow, pow_, pob, out);
}

// round 11
// speedup vs baseline: 1.5738x; 1.1166x over previous
#include <cuda_runtime.h>
#include <cuda_bf16.h>
#include <cstdint>

#define NB    64
#define TE    200
#define ENCD  256
#define DECD  1024
#define HATT  128
#define NCONV 32
#define KCONV 31
#define PADC  15
#define PRE   256
#define NC    80
#define TFEAT 1000
#define SSTEPS 500
#define HSZ   (NB*DECD)

#define LOGIT_OFF 5120000
#define ATTW_OFF  5184000

#define GRID  128
#define THR   512

// dynamic smem (bytes): double-buffered W(hi/lo) 128x64 bf16 + act(hi/lo) 64x64 bf16
#define SM_AWH(b)  (1024  + (b)*16384)
#define SM_AWL(b)  (33792 + (b)*16384)
#define SM_BXH(b)  (66560 + (b)*8192)
#define SM_BXL(b)  (82944 + (b)*8192)
#define SM_TOTAL   99328
#define SM_F_OFF   256      // float index of att/outproj scratch (byte 1024)

// ---------------- scratch ----------------
__device__ float g_pm[NB*TE*HATT];
__device__ float g_Wck[HATT*32];
__device__ float g_preH[SSTEPS*NB*PRE];
__device__ float g_P[SSTEPS*NB*PRE];
__device__ __nv_bfloat16 g_Ph[SSTEPS*NB*PRE], g_Pl[SSTEPS*NB*PRE];
__device__ __nv_bfloat16 g_W0h[4096*1536], g_W0l[4096*1536];
__device__ __nv_bfloat16 g_W1h[4096*2048], g_W1l[4096*2048];
__device__ float g_part[4*4096*64];      // [kq][row][batch]
__device__ float g_acf[2*NB*ENCD];
__device__ __nv_bfloat16 g_ach[NB*ENCD], g_acl[NB*ENCD];
__device__ float g_h0f[HSZ], g_c0[HSZ];
__device__ float g_h1f[HSZ], g_c1[HSZ];
__device__ __nv_bfloat16 g_h0h[HSZ], g_h0l[HSZ], g_h1h[HSZ], g_h1l[HSZ];
__device__ float g_acc[NB*TE];
__device__ float g_b40[4096], g_b41[4096];
__device__ unsigned g_flags[GRID];

// ---------------- warp MMA helpers (portable sm_80+, OK on sm_103 non-a) -------
__device__ __forceinline__ uint32_t smem_u32_of(const void* p) {
    uint32_t a;
    asm("{ .reg .u64 t; cvta.to.shared.u64 t, %1; cvt.u32.u64 %0, t; }" : "=r"(a) : "l"(p));
    return a;
}
__device__ __forceinline__ void ldsm4(uint32_t* r, uint32_t addr) {
    asm volatile("ldmatrix.sync.aligned.m8n8.x4.shared.b16 {%0,%1,%2,%3}, [%4];"
        : "=r"(r[0]), "=r"(r[1]), "=r"(r[2]), "=r"(r[3]) : "r"(addr));
}
__device__ __forceinline__ void mma16816(float* c, const uint32_t* a, uint32_t b0, uint32_t b1) {
    asm volatile("mma.sync.aligned.m16n8k16.row.col.f32.bf16.bf16.f32 "
        "{%0,%1,%2,%3}, {%4,%5,%6,%7}, {%8,%9}, {%0,%1,%2,%3};"
        : "+f"(c[0]), "+f"(c[1]), "+f"(c[2]), "+f"(c[3])
        : "r"(a[0]), "r"(a[1]), "r"(a[2]), "r"(a[3]), "r"(b0), "r"(b1));
}

// ---------------- grid barrier: per-block flags + parallel poll ----------------
__device__ __forceinline__ void gbar(unsigned gen) {
    __syncthreads();
    if (threadIdx.x == 0) {
        __threadfence();
        *((volatile unsigned*)&g_flags[blockIdx.x]) = gen;
    }
    if (threadIdx.x < GRID) {
        volatile unsigned* f = g_flags + threadIdx.x;
        while (*f < gen) { __nanosleep(40); }
    }
    __threadfence();
    __syncthreads();
}

// ---------------- setup kernels ----------------
__global__ void k_wck(const float* __restrict__ watt, const float* __restrict__ cw) {
    int idx = blockIdx.x * blockDim.x + threadIdx.x;
    if (idx >= HATT * 32) return;
    int h = idx >> 5, k = idx & 31;
    float s = 0.f;
    if (k < KCONV) {
        #pragma unroll
        for (int c = 0; c < NCONV; c++) s += watt[h * NCONV + c] * cw[c * KCONV + k];
    }
    g_Wck[idx] = s;
}

__global__ void k_init(const float* __restrict__ b0a, const float* __restrict__ b0b,
                       const float* __restrict__ b1a, const float* __restrict__ b1b) {
    int i = blockIdx.x * blockDim.x + threadIdx.x;
    if (i < GRID) g_flags[i] = 0u;
    if (i < HSZ) {
        g_h0f[i] = 0.f; g_h1f[i] = 0.f; g_c0[i] = 0.f; g_c1[i] = 0.f;
        __nv_bfloat16 z = __float2bfloat16(0.f);
        g_h0h[i] = z; g_h0l[i] = z; g_h1h[i] = z; g_h1l[i] = z;
    }
    if (i < 4096) { g_b40[i] = b0a[i] + b0b[i]; g_b41[i] = b1a[i] + b1b[i]; }
}

__global__ void k_cvtW(const float* __restrict__ wih, const float* __restrict__ whh,
                       int KIH, int KT, __nv_bfloat16* __restrict__ Wh,
                       __nv_bfloat16* __restrict__ Wl, int total) {
    int idx = blockIdx.x * blockDim.x + threadIdx.x;
    if (idx >= total) return;
    int r = idx / KT, k = idx - r * KT;
    float v = (k < KIH) ? wih[(size_t)r * KIH + k] : whh[(size_t)r * 1024 + (k - KIH)];
    __nv_bfloat16 hi = __float2bfloat16(v);
    Wh[idx] = hi;
    Wl[idx] = __float2bfloat16(v - __bfloat162float(hi));
}

__global__ void k_cvtP() {
    int idx = blockIdx.x * blockDim.x + threadIdx.x;
    if (idx >= SSTEPS * NB * PRE) return;
    float v = g_P[idx];
    __nv_bfloat16 hi = __float2bfloat16(v);
    g_Ph[idx] = hi;
    g_Pl[idx] = __float2bfloat16(v - __bfloat162float(hi));
}

// ---------------- setup GEMM (validated):  C = A*W^T (+bias, relu) -------------
template<int LOADER>
__global__ __launch_bounds__(256) void k_gemm(
    const float* __restrict__ A, const float* __restrict__ W,
    const float* __restrict__ bias, float* __restrict__ Cout,
    int N, int K, int lda, const float* __restrict__ ft, int relu)
{
    __shared__ float As[16][68];
    __shared__ float Ws[16][68];
    int tid  = threadIdx.x;
    int mb = blockIdx.x * 64, nb = blockIdx.y * 64;
    int la_m = tid >> 2, la_k = (tid & 3) << 2;
    int tx = tid & 15, ty = tid >> 4;
    float acc[4][4] = {};

    for (int k0 = 0; k0 < K; k0 += 16) {
        float4 av;
        if (LOADER == 0) {
            av = *reinterpret_cast<const float4*>(A + (size_t)(mb + la_m) * lda + k0 + la_k);
        } else {
            int row = mb + la_m;
            int s = row >> 6, bb = row & 63;
            float t0 = 0.f, t1 = 0.f, t2 = 0.f, t3 = 0.f;
            if (s > 0) {
                int base = (s - 1) * 2;
                int k = k0 + la_k;
                const float* fb = ft + (size_t)bb * NC * TFEAT;
                t0 = fb[(k % NC) * TFEAT + base + k / NC]; k++;
                t1 = fb[(k % NC) * TFEAT + base + k / NC]; k++;
                t2 = fb[(k % NC) * TFEAT + base + k / NC]; k++;
                t3 = fb[(k % NC) * TFEAT + base + k / NC];
            }
            av = make_float4(t0, t1, t2, t3);
        }
        As[la_k][la_m] = av.x; As[la_k+1][la_m] = av.y;
        As[la_k+2][la_m] = av.z; As[la_k+3][la_m] = av.w;
        float4 wv = *reinterpret_cast<const float4*>(W + (size_t)(nb + la_m) * K + k0 + la_k);
        Ws[la_k][la_m] = wv.x; Ws[la_k+1][la_m] = wv.y;
        Ws[la_k+2][la_m] = wv.z; Ws[la_k+3][la_m] = wv.w;
        __syncthreads();
        #pragma unroll
        for (int k = 0; k < 16; k++) {
            float4 a = *reinterpret_cast<const float4*>(&As[k][ty << 2]);
            float4 b = *reinterpret_cast<const float4*>(&Ws[k][tx << 2]);
            acc[0][0] += a.x*b.x; acc[0][1] += a.x*b.y; acc[0][2] += a.x*b.z; acc[0][3] += a.x*b.w;
            acc[1][0] += a.y*b.x; acc[1][1] += a.y*b.y; acc[1][2] += a.y*b.z; acc[1][3] += a.y*b.w;
            acc[2][0] += a.z*b.x; acc[2][1] += a.z*b.y; acc[2][2] += a.z*b.z; acc[2][3] += a.z*b.w;
            acc[3][0] += a.w*b.x; acc[3][1] += a.w*b.y; acc[3][2] += a.w*b.z; acc[3][3] += a.w*b.w;
        }
        __syncthreads();
    }
    #pragma unroll
    for (int i = 0; i < 4; i++) {
        int m = mb + (ty << 2) + i;
        #pragma unroll
        for (int j = 0; j < 4; j++) {
            int n = nb + (tx << 2) + j;
            float v = acc[i][j] + bias[n];
            if (relu) v = fmaxf(v, 0.f);
            Cout[(size_t)m * N + n] = v;
        }
    }
}

// ---------------- GEMM-phase chunk load/store (validated layout) ----------------
struct Regs6 { uint4 v[6]; };

__device__ __forceinline__ void ldg_chunk(Regs6& R,
    const __nv_bfloat16* __restrict__ Wh, const __nv_bfloat16* __restrict__ Wl,
    const __nv_bfloat16* __restrict__ Bh, const __nv_bfloat16* __restrict__ Bl,
    int bstr, int KT, int rowbase, int k0, int koff, int tid)
{
    #pragma unroll
    for (int j = 0; j < 2; j++) {
        int seg = tid + j * 512;
        int r = seg >> 3, cs = seg & 7;
        size_t off = (size_t)(rowbase + r) * KT + k0 + cs * 8;
        R.v[j]     = *reinterpret_cast<const uint4*>(Wh + off);
        R.v[2 + j] = *reinterpret_cast<const uint4*>(Wl + off);
    }
    {
        int r = tid >> 3, cs = tid & 7;
        size_t off = (size_t)r * bstr + koff + cs * 8;
        R.v[4] = *reinterpret_cast<const uint4*>(Bh + off);
        R.v[5] = *reinterpret_cast<const uint4*>(Bl + off);
    }
}

__device__ __forceinline__ void sts_chunk(const Regs6& R, char* sm, int buf, int tid) {
    #pragma unroll
    for (int j = 0; j < 2; j++) {
        int seg = tid + j * 512;
        int r = seg >> 3, cs = seg & 7;
        uint32_t off = r * 128 + cs * 16;
        uint32_t sw = off ^ ((off >> 3) & 0x70);
        *reinterpret_cast<uint4*>(sm + SM_AWH(buf) + sw) = R.v[j];
        *reinterpret_cast<uint4*>(sm + SM_AWL(buf) + sw) = R.v[2 + j];
    }
    {
        int r = tid >> 3, cs = tid & 7;
        uint32_t off = r * 128 + cs * 16;
        uint32_t sw = off ^ ((off >> 3) & 0x70);
        *reinterpret_cast<uint4*>(sm + SM_BXH(buf) + sw) = R.v[4];
        *reinterpret_cast<uint4*>(sm + SM_BXL(buf) + sw) = R.v[5];
    }
}

// ---------------- one LSTM GEMM phase via mma.sync (bf16 3-term split) ---------
template<int L>
__device__ void gemm_phase(char* sm, uint32_t smb, int rb, int kq, int s,
    const __nv_bfloat16* __restrict__ Wh, const __nv_bfloat16* __restrict__ Wl,
    int tid)
{
    constexpr int KT = L ? 2048 : 1536;
    constexpr int NCH = L ? 8 : 6;
    const int rowbase = rb * 128;
    const int kqbase = kq * (KT / 4);

    const int warp = tid >> 5, lane = tid & 31;
    const int mt = warp >> 1;            // 0..7
    const int nh = (warp & 1) * 32;      // 0 or 32

    const int ar = mt * 16 + (lane & 15);
    const uint32_t aoff0 = (uint32_t)ar * 128 + (uint32_t)(lane >> 4) * 16;
    const uint32_t amx = (uint32_t)(ar & 7) << 4;
    const int bn0 = nh + ((lane >> 4) & 1) * 8 + (lane & 7);
    const uint32_t boff0 = (uint32_t)bn0 * 128 + (uint32_t)((lane >> 3) & 1) * 16;
    const uint32_t bmx = (uint32_t)(bn0 & 7) << 4;

    auto resolveB = [&](int k0, const __nv_bfloat16*& bh, const __nv_bfloat16*& bl,
                        int& bstr, int& koff) {
        if (L == 0) {
            if (k0 < 256)      { bh = g_ach; bl = g_acl; bstr = 256; koff = k0; }
            else if (k0 < 512) { bh = g_Ph + (size_t)s * NB * PRE;
                                 bl = g_Pl + (size_t)s * NB * PRE; bstr = 256; koff = k0 - 256; }
            else               { bh = g_h0h; bl = g_h0l; bstr = 1024; koff = k0 - 512; }
        } else {
            bstr = 1024;
            if (k0 < 1024) { bh = g_h0h; bl = g_h0l; koff = k0; }
            else           { bh = g_h1h; bl = g_h1l; koff = k0 - 1024; }
        }
    };

    float acc[4][4];
    #pragma unroll
    for (int nt = 0; nt < 4; nt++)
        #pragma unroll
        for (int q = 0; q < 4; q++) acc[nt][q] = 0.f;

    {   // prologue: chunk 0 -> buf 0
        Regs6 R; const __nv_bfloat16 *bh, *bl; int bstr, koff;
        resolveB(kqbase, bh, bl, bstr, koff);
        ldg_chunk(R, Wh, Wl, bh, bl, bstr, KT, rowbase, kqbase, koff, tid);
        sts_chunk(R, sm, 0, tid);
    }
    __syncthreads();

    for (int i = 0; i < NCH; i++) {
        Regs6 R;
        const int buf = i & 1;
        const bool more = (i + 1 < NCH);
        if (more) {
            int k0 = kqbase + (i + 1) * 64;
            const __nv_bfloat16 *bh, *bl; int bstr, koff;
            resolveB(k0, bh, bl, bstr, koff);
            ldg_chunk(R, Wh, Wl, bh, bl, bstr, KT, rowbase, k0, koff, tid);
        }
        const uint32_t awh = smb + SM_AWH(buf), awl = smb + SM_AWL(buf);
        const uint32_t bxh = smb + SM_BXH(buf), bxl = smb + SM_BXL(buf);
        #pragma unroll
        for (int kk = 0; kk < 4; kk++) {
            const uint32_t col = kk * 32;
            uint32_t ah[4], al[4], bh0[4], bh1[4], bl0[4], bl1[4];
            const uint32_t aof = (aoff0 + col) ^ amx;
            ldsm4(ah, awh + aof);
            ldsm4(al, awl + aof);
            const uint32_t bof = (boff0 + col) ^ bmx;
            ldsm4(bh0, bxh + bof);
            ldsm4(bh1, bxh + bof + 2048);
            ldsm4(bl0, bxl + bof);
            ldsm4(bl1, bxl + bof + 2048);
            mma16816(acc[0], ah, bh0[0], bh0[1]);
            mma16816(acc[1], ah, bh0[2], bh0[3]);
            mma16816(acc[2], ah, bh1[0], bh1[1]);
            mma16816(acc[3], ah, bh1[2], bh1[3]);
            mma16816(acc[0], ah, bl0[0], bl0[1]);
            mma16816(acc[1], ah, bl0[2], bl0[3]);
            mma16816(acc[2], ah, bl1[0], bl1[1]);
            mma16816(acc[3], ah, bl1[2], bl1[3]);
            mma16816(acc[0], al, bh0[0], bh0[1]);
            mma16816(acc[1], al, bh0[2], bh0[3]);
            mma16816(acc[2], al, bh1[0], bh1[1]);
            mma16816(acc[3], al, bh1[2], bh1[3]);
        }
        // single sync per chunk: sts writes buf^1 (read last at i-1, fenced by
        // the sync at end of i-1; next read at i+1, fenced by this sync)
        if (more) sts_chunk(R, sm, buf ^ 1, tid);
        __syncthreads();
    }

    // epilogue: write fp32 partials
    {
        const int trow = lane >> 2, tcol = (lane & 3) * 2;
        #pragma unroll
        for (int nt = 0; nt < 4; nt++) {
            int row = rowbase + mt * 16 + trow;
            int col = nh + nt * 8 + tcol;
            float* dst = g_part + ((size_t)kq * 4096 + row) * 64 + col;
            *reinterpret_cast<float2*>(dst) = make_float2(acc[nt][0], acc[nt][1]);
            *reinterpret_cast<float2*>(dst + 8 * 64) = make_float2(acc[nt][2], acc[nt][3]);
        }
    }
}

// ---------------- pointwise + zoneout + bf16 split ----------------
__device__ void pw_phase(int u0, const float* __restrict__ b4,
    float* __restrict__ hf, __nv_bfloat16* __restrict__ hh, __nv_bfloat16* __restrict__ hl,
    float* __restrict__ cf, int tid)
{
    int ul = tid >> 6, bat = tid & 63;
    int u = u0 + ul;
    float g[4];
    #pragma unroll
    for (int gg = 0; gg < 4; gg++) {
        int row = gg * 1024 + u;
        float v = b4[row];
        #pragma unroll
        for (int kq = 0; kq < 4; kq++)
            v += g_part[((size_t)kq * 4096 + row) * 64 + bat];
        g[gg] = v;
    }
    int idx = bat * 1024 + u;
    float cold = cf[idx], hold = hf[idx];
    float si = 1.f / (1.f + __expf(-g[0]));
    float sf = 1.f / (1.f + __expf(-g[1]));
    float so = 1.f / (1.f + __expf(-g[3]));
    float c2 = sf * cold + si * tanhf(g[2]);
    float h2 = so * tanhf(c2);
    float hn = 0.1f * hold + 0.9f * h2;
    float cn = 0.1f * cold + 0.9f * c2;
    hf[idx] = hn; cf[idx] = cn;
    __nv_bfloat16 hi = __float2bfloat16(hn);
    hh[idx] = hi;
    hl[idx] = __float2bfloat16(hn - __bfloat162float(hi));
}

// ---------------- attention (512-thread; validated math; float4 dp) ------------
__device__ void att_step(float* __restrict__ smf, int s, int b,
    const float* __restrict__ enc, const int* __restrict__ text_len,
    const float* __restrict__ wdec, const float* __restrict__ watt,
    const float* __restrict__ watt_b, float* __restrict__ attw_out)
{
    float* sWck = smf;                  // 4224
    float* apad = smf + 4224;           // 232
    float* dp   = smf + 4456;           // 128
    float* w_s  = smf + 4584;           // 128
    float* sE   = smf + 4712;           // 200
    float* red  = smf + 4912;           // 32
    float* hrow = smf + 4960;           // 1024 (h0 row staged in smem)
    int tid = threadIdx.x, lane = tid & 31, wid = tid >> 5;
    int len = text_len[b];

    for (int i = tid; i < HATT * 33; i += THR) {
        int h = i / 33, k = i - h * 33;
        sWck[i] = (k < 31) ? g_Wck[h * 32 + k] : 0.f;
    }
    if (tid < 16)  apad[tid] = 0.f;
    if (tid < 17)  apad[215 + tid] = 0.f;
    if (tid < 200) {
        float v = (s == 0) ? ((tid < len) ? 1.f / (float)len : 0.f) : g_acc[b * TE + tid];
        apad[PADC + tid] = v;
    }
    if (tid < HATT) w_s[tid] = watt[tid];
    if (tid < DECD / 4)
        reinterpret_cast<float4*>(hrow)[tid] =
            reinterpret_cast<const float4*>(g_h0f + b * DECD)[tid];
    __syncthreads();

    // dp[h] = h0[b] . wdec[h] — float4 loads, one warp per 8 rows
    {
        const float4* hr4 = reinterpret_cast<const float4*>(hrow);
        for (int h = wid; h < HATT; h += 16) {
            const float4* wr = reinterpret_cast<const float4*>(wdec + (size_t)h * DECD);
            float p = 0.f;
            #pragma unroll
            for (int j = lane; j < 256; j += 32) {
                float4 w = wr[j]; float4 hv = hr4[j];
                p += w.x*hv.x + w.y*hv.y + w.z*hv.z + w.w*hv.w;
            }
            #pragma unroll
            for (int o = 16; o; o >>= 1) p += __shfl_xor_sync(0xffffffffu, p, o);
            if (lane == 0) dp[h] = p;
        }
    }
    __syncthreads();

    const float wb0 = watt_b[0];
    for (int it = 0; it < 13; it++) {
        int t = it * 16 + wid;
        if (t < TE) {
            const float* pmrow = g_pm + ((size_t)(b * TE + t)) * HATT;
            float esum = 0.f;
            #pragma unroll
            for (int hh = 0; hh < 4; hh++) {
                int h = lane + (hh << 5);
                const float* wc = sWck + h * 33;
                float conv = 0.f;
                #pragma unroll
                for (int k = 0; k < 31; k++) conv += wc[k] * apad[t + k];
                float x = conv + dp[h] + pmrow[h];
                float ez = __expf(2.f * x);
                float th = 1.f - __fdividef(2.f, ez + 1.f);
                esum += w_s[h] * th;
            }
            #pragma unroll
            for (int o = 16; o; o >>= 1) esum += __shfl_xor_sync(0xffffffffu, esum, o);
            if (lane == 0) sE[t] = esum + wb0;
        }
    }
    __syncthreads();

    float e = (tid < len) ? sE[tid] : -1e30f;
    float mx = e;
    #pragma unroll
    for (int o = 16; o; o >>= 1) mx = fmaxf(mx, __shfl_xor_sync(0xffffffffu, mx, o));
    if (lane == 0) red[wid] = mx;
    __syncthreads();
    if (tid == 0) {
        float mm = red[0];
        for (int i = 1; i < 16; i++) mm = fmaxf(mm, red[i]);
        red[16] = mm;
    }
    __syncthreads();
    mx = red[16];
    float ex = (tid < 200) ? __expf(e - mx) : 0.f;
    float sm = ex;
    #pragma unroll
    for (int o = 16; o; o >>= 1) sm += __shfl_xor_sync(0xffffffffu, sm, o);
    if (lane == 0) red[wid] = sm;
    __syncthreads();
    if (tid == 0) {
        float ss = 0.f;
        for (int i = 0; i < 16; i++) ss += red[i];
        red[17] = ss;
    }
    __syncthreads();
    float inv = 1.f / red[17];
    __syncthreads();
    if (tid < 200) {
        float aw = ex * inv;
        sE[tid] = aw;
        attw_out[((size_t)b * SSTEPS + s) * TE + tid] = aw;
        float an = (s == 0) ? aw : g_acc[b * TE + tid] + aw;
        g_acc[b * TE + tid] = an;
    }
    __syncthreads();

    if (tid < ENCD) {
        int c = tid;
        const float* er = enc + ((size_t)b * TE) * ENCD + c;
        float a0 = 0.f, a1 = 0.f, a2 = 0.f, a3 = 0.f;
        #pragma unroll 4
        for (int t = 0; t < TE; t += 4) {
            a0 += sE[t]     * er[(size_t)t * ENCD];
            a1 += sE[t + 1] * er[(size_t)(t + 1) * ENCD];
            a2 += sE[t + 2] * er[(size_t)(t + 2) * ENCD];
            a3 += sE[t + 3] * er[(size_t)(t + 3) * ENCD];
        }
        float ac = (a0 + a1) + (a2 + a3);
        g_acf[(size_t)(s & 1) * NB * ENCD + b * ENCD + c] = ac;
        __nv_bfloat16 hi = __float2bfloat16(ac);
        g_ach[b * ENCD + c] = hi;
        g_acl[b * ENCD + c] = __float2bfloat16(ac - __bfloat162float(hi));
    }
    __syncthreads();
}

// ---------------- output projection (512-thread, float4 rows) ------------------
__device__ void outproj(float* __restrict__ smf, int s, int b,
    const float* __restrict__ fw, const float* __restrict__ pwm,
    const float* __restrict__ pb, float* __restrict__ out)
{
    float* hcs = smf;
    int tid = threadIdx.x, lane = tid & 31, wid = tid >> 5;
    const float* acb = g_acf + (size_t)(s & 1) * NB * ENCD;
    for (int i = tid; i < 1280; i += THR)
        hcs[i] = (i < 1024) ? g_h1f[b * DECD + i] : acb[b * ENCD + (i - 1024)];
    __syncthreads();
    const float4* h4 = reinterpret_cast<const float4*>(hcs);
    for (int o = wid; o < 162; o += 16) {
        const float* row = (o < 160) ? (fw + (size_t)o * 1280) : (pwm + (size_t)(o - 160) * 1280);
        const float4* r4 = reinterpret_cast<const float4*>(row);
        float sum = 0.f;
        #pragma unroll
        for (int i = lane; i < 320; i += 32) {
            float4 rv = r4[i], hv = h4[i];
            sum += rv.x*hv.x + rv.y*hv.y + rv.z*hv.z + rv.w*hv.w;
        }
        #pragma unroll
        for (int of = 16; of; of >>= 1) sum += __shfl_xor_sync(0xffffffffu, sum, of);
        if (lane == 0) {
            if (o < 160) {
                int r = o / NC, ch = o % NC;
                out[(size_t)b * NC * TFEAT + (size_t)ch * TFEAT + s * 2 + r] = sum;
            } else {
                out[LOGIT_OFF + (size_t)b * TFEAT + s * 2 + (o - 160)] = sum + pb[o - 160];
            }
        }
    }
    __syncthreads();
}

// ---------------- persistent decoder ----------------
__global__ void __launch_bounds__(THR, 1) k_decoder(
    const float* __restrict__ enc, const int* __restrict__ tlen,
    const float* __restrict__ wdec, const float* __restrict__ watt,
    const float* __restrict__ wattb,
    const float* __restrict__ fow, const float* __restrict__ pow_,
    const float* __restrict__ pob, float* __restrict__ out)
{
    extern __shared__ char sm[];
    float* smf = reinterpret_cast<float*>(sm) + SM_F_OFF;
    uint32_t smb = smem_u32_of(sm);
    int tid = threadIdx.x;
    int blk = blockIdx.x;
    int rb = blk >> 2, kq = blk & 3;
    float* attw = out + ATTW_OFF;
    unsigned gen = 0;

    // phase 0: attention for step 0 (h0 = 0, uniform prior)
    if (blk < 64)
        att_step(smf, 0, blk, enc, tlen, wdec, watt, wattb, attw);
    gen++; gbar(gen);

    for (int s = 0; s < SSTEPS; s++) {
        // A: lstm0 GEMM
        gemm_phase<0>(sm, smb, rb, kq, s, g_W0h, g_W0l, tid);
        gen++; gbar(gen);
        // B: pw0 (all) + outproj(s-1) on blocks >= 64
        pw_phase(blk * 8, g_b40, g_h0f, g_h0h, g_h0l, g_c0, tid);
        if (blk >= 64 && s >= 1)
            outproj(smf, s - 1, blk - 64, fow, pow_, pob, out);
        gen++; gbar(gen);
        // C: lstm1 GEMM
        gemm_phase<1>(sm, smb, rb, kq, s, g_W1h, g_W1l, tid);
        gen++; gbar(gen);
        // D: pw1 (all) + attention(s+1) on blocks < 64
        pw_phase(blk * 8, g_b41, g_h1f, g_h1h, g_h1l, g_c1, tid);
        if (blk < 64 && s + 1 < SSTEPS)
            att_step(smf, s + 1, blk, enc, tlen, wdec, watt, wattb, attw);
        gen++; gbar(gen);
    }
    // tail: outproj for the last step
    if (blk >= 64)
        outproj(smf, SSTEPS - 1, blk - 64, fow, pow_, pob, out);
}

// ---------------- host ----------------
static float* symaddr(const void* sym) {
    void* p = nullptr;
    cudaGetSymbolAddress(&p, sym);
    return (float*)p;
}

extern "C" void kernel_launch(void* const* d_in, const int* in_sizes, int n_in,
                              void* d_out, int out_size)
{
    const float* enc    = (const float*)d_in[0];
    const int*   tlen   = (const int*)  d_in[1];
    const float* ft     = (const float*)d_in[2];
    const float* enc_w  = (const float*)d_in[3];
    const float* enc_b  = (const float*)d_in[4];
    const float* dec_w  = (const float*)d_in[5];
    const float* att_w  = (const float*)d_in[6];
    const float* conv_w = (const float*)d_in[7];
    const float* ww     = (const float*)d_in[8];
    const float* wbb    = (const float*)d_in[9];
    const float* pw0    = (const float*)d_in[10];
    const float* pb0    = (const float*)d_in[11];
    const float* pw1    = (const float*)d_in[12];
    const float* pb1    = (const float*)d_in[13];
    const float* l0wih  = (const float*)d_in[14];
    const float* l0whh  = (const float*)d_in[15];
    const float* l0bih  = (const float*)d_in[16];
    const float* l0bhh  = (const float*)d_in[17];
    const float* l1wih  = (const float*)d_in[18];
    const float* l1whh  = (const float*)d_in[19];
    const float* l1bih  = (const float*)d_in[20];
    const float* l1bhh  = (const float*)d_in[21];
    const float* fow    = (const float*)d_in[22];
    const float* pow_   = (const float*)d_in[23];
    const float* pob    = (const float*)d_in[24];
    float* out = (float*)d_out;

    float* pm_p = symaddr(g_pm);
    float* preH = symaddr(g_preH);
    float* Pp   = symaddr(g_P);
    __nv_bfloat16* W0h = (__nv_bfloat16*)symaddr(g_W0h);
    __nv_bfloat16* W0l = (__nv_bfloat16*)symaddr(g_W0l);
    __nv_bfloat16* W1h = (__nv_bfloat16*)symaddr(g_W1h);
    __nv_bfloat16* W1l = (__nv_bfloat16*)symaddr(g_W1l);

    static int smem_set = 0;
    if (!smem_set) {
        cudaFuncSetAttribute(k_decoder, cudaFuncAttributeMaxDynamicSharedMemorySize, SM_TOTAL);
        smem_set = 1;
    }

    k_wck<<<16, 256>>>(att_w, conv_w);
    k_init<<<(HSZ + 255) / 256, 256>>>(l0bih, l0bhh, l1bih, l1bhh);
    k_gemm<0><<<dim3(200, 2), 256>>>(enc, enc_w, enc_b, pm_p, 128, 256, 256, nullptr, 0);
    k_gemm<1><<<dim3(500, 4), 256>>>(nullptr, pw0, pb0, preH, 256, 160, 0, ft, 1);
    k_gemm<0><<<dim3(500, 4), 256>>>(preH, pw1, pb1, Pp, 256, 256, 256, nullptr, 1);
    k_cvtW<<<(4096 * 1536 + 255) / 256, 256>>>(l0wih, l0whh, 512, 1536, W0h, W0l, 4096 * 1536);
    k_cvtW<<<(4096 * 2048 + 255) / 256, 256>>>(l1wih, l1whh, 1024, 2048, W1h, W1l, 4096 * 2048);
    k_cvtP<<<(SSTEPS * NB * PRE + 255) / 256, 256>>>();

    k_decoder<<<GRID, THR, SM_TOTAL>>>(
        enc, tlen, dec_w, ww, wbb, fow, pow_, pob, out);
}